// round 3
// baseline (speedup 1.0000x reference)
#include <cuda_runtime.h>

// ---------------------------------------------------------------------------
// MultiHeadAttention: out = proj_o( softmax_causal( (xWq^T+bq)(xWk^T+bk)^T / 8 ) (xWv^T+bv) )
// B=4, S=2048, D=1024, H=16, DK=64.  All fp32.
//
// Round 1: robust FFMA implementation.
//   - sgemm_nt_bias: C[M,N] = A[M,K] @ W[N,K]^T + bias  (128x128x8 tiles, 8x8/thread)
//   - attn_kernel:  flash attention, 64-query tile/block, causal tile skip,
//                   q/k/v kept in [B,S,H*DK] layout (no transposes).
// ---------------------------------------------------------------------------

#define B_SZ   4
#define S_LEN  2048
#define D_DIM  1024
#define NH     16
#define DKH    64
#define NROWS  (B_SZ * S_LEN)          // 8192

// Scratch (static device globals -- allocation rules forbid cudaMalloc)
__device__ float g_q[NROWS * D_DIM];
__device__ float g_k[NROWS * D_DIM];
__device__ float g_v[NROWS * D_DIM];
__device__ float g_vals[NROWS * D_DIM];

// ---------------------------------------------------------------------------
// SGEMM:  C = A @ W^T + bias.   A:[M,K] row-major, W:[N,K] row-major.
// Block tile 128x128, K-tile 8, 256 threads, 8x8 outputs per thread.
// ---------------------------------------------------------------------------
__global__ void __launch_bounds__(256)
sgemm_nt_bias(const float* __restrict__ A, const float* __restrict__ W,
              const float* __restrict__ bias, float* __restrict__ C,
              int M, int N, int K)
{
    __shared__ float As[8][128];
    __shared__ float Ws[8][128];

    const int tid = threadIdx.x;
    const int bm  = blockIdx.y * 128;
    const int bn  = blockIdx.x * 128;
    const int tx  = tid & 15;          // 0..15  (col group)
    const int ty  = tid >> 4;          // 0..15  (row group)
    const int lrow = tid >> 1;         // 0..127 (loader row)
    const int lk4  = (tid & 1) << 2;   // 0 or 4 (loader k-offset)

    const float* Ap = A + (size_t)(bm + lrow) * K + lk4;
    const float* Wp = W + (size_t)(bn + lrow) * K + lk4;

    float acc[8][8];
    #pragma unroll
    for (int i = 0; i < 8; i++)
        #pragma unroll
        for (int j = 0; j < 8; j++) acc[i][j] = 0.f;

    for (int k0 = 0; k0 < K; k0 += 8) {
        float4 a4 = *(const float4*)(Ap + k0);
        float4 w4 = *(const float4*)(Wp + k0);
        As[lk4+0][lrow] = a4.x; As[lk4+1][lrow] = a4.y;
        As[lk4+2][lrow] = a4.z; As[lk4+3][lrow] = a4.w;
        Ws[lk4+0][lrow] = w4.x; Ws[lk4+1][lrow] = w4.y;
        Ws[lk4+2][lrow] = w4.z; Ws[lk4+3][lrow] = w4.w;
        __syncthreads();

        #pragma unroll
        for (int kk = 0; kk < 8; kk++) {
            float4 a0 = *(const float4*)(&As[kk][ty*8]);
            float4 a1 = *(const float4*)(&As[kk][ty*8+4]);
            float4 w0 = *(const float4*)(&Ws[kk][tx*8]);
            float4 w1 = *(const float4*)(&Ws[kk][tx*8+4]);
            float af[8] = {a0.x,a0.y,a0.z,a0.w,a1.x,a1.y,a1.z,a1.w};
            float wf[8] = {w0.x,w0.y,w0.z,w0.w,w1.x,w1.y,w1.z,w1.w};
            #pragma unroll
            for (int i = 0; i < 8; i++)
                #pragma unroll
                for (int j = 0; j < 8; j++)
                    acc[i][j] = fmaf(af[i], wf[j], acc[i][j]);
        }
        __syncthreads();
    }

    float bfrag[8];
    #pragma unroll
    for (int j = 0; j < 8; j++) bfrag[j] = bias[bn + tx*8 + j];

    #pragma unroll
    for (int i = 0; i < 8; i++) {
        const size_t row = (size_t)(bm + ty*8 + i);
        float* cp = C + row * N + bn + tx*8;
        float4 o0 = {acc[i][0]+bfrag[0], acc[i][1]+bfrag[1],
                     acc[i][2]+bfrag[2], acc[i][3]+bfrag[3]};
        float4 o1 = {acc[i][4]+bfrag[4], acc[i][5]+bfrag[5],
                     acc[i][6]+bfrag[6], acc[i][7]+bfrag[7]};
        *(float4*)cp     = o0;
        *(float4*)(cp+4) = o1;
    }
}

// ---------------------------------------------------------------------------
// Flash attention, causal.  One block = 64 query rows of one (b,h).
// 256 threads: thread t -> query row r = t/4, group g = t%4.
//   scores:  thread owns j in {g, g+4, ..., g+60}  (16 scores)
//   output:  thread owns dk float4-chunks {g, g+4, g+8, g+12} (16 floats)
// Row stride in smem = 68 floats -> all LDS.128 patterns bank-conflict-free.
// q/k/v layout: [B,S,H*DK]; head h's row s at base + s*D + h*64.
// ---------------------------------------------------------------------------
#define QT     64
#define PADF   68
#define ATTN_SMEM (4 * QT * PADF * (int)sizeof(float))   // 69632 B

__global__ void __launch_bounds__(256)
attn_kernel()
{
    extern __shared__ float sm[];
    float* Qs = sm;
    float* Ks = Qs + QT*PADF;
    float* Vs = Ks + QT*PADF;
    float* Ps = Vs + QT*PADF;

    const int tid = threadIdx.x;
    const int qt  = blockIdx.x;
    const int bh  = blockIdx.y;
    const int b   = bh >> 4;
    const int h   = bh & 15;
    const size_t base = (size_t)b * S_LEN * D_DIM + (size_t)h * DKH;
    const int q0 = qt * QT;

    // load Q tile (64 rows x 64 floats)
    for (int idx = tid; idx < QT*16; idx += 256) {
        int row = idx >> 4, c = (idx & 15) << 2;
        *(float4*)(Qs + row*PADF + c) =
            *(const float4*)(g_q + base + (size_t)(q0+row)*D_DIM + c);
    }

    const int r = tid >> 2;
    const int g = tid & 3;
    float acc[16];
    #pragma unroll
    for (int i = 0; i < 16; i++) acc[i] = 0.f;
    float m_run = -1e30f, l_run = 0.f;

    for (int jt = 0; jt <= qt; jt++) {
        __syncthreads();   // everyone done with previous Ks/Vs
        const int k0 = jt * QT;
        for (int idx = tid; idx < QT*16; idx += 256) {
            int row = idx >> 4, c = (idx & 15) << 2;
            *(float4*)(Ks + row*PADF + c) =
                *(const float4*)(g_k + base + (size_t)(k0+row)*D_DIM + c);
            *(float4*)(Vs + row*PADF + c) =
                *(const float4*)(g_v + base + (size_t)(k0+row)*D_DIM + c);
        }
        __syncthreads();

        // ---- scores: s[i] = Q[r] . K[g+4i] ----
        float s[16];
        #pragma unroll
        for (int i = 0; i < 16; i++) s[i] = 0.f;
        #pragma unroll
        for (int d4 = 0; d4 < 16; d4++) {
            const float4 q4 = *(const float4*)(Qs + r*PADF + d4*4);
            #pragma unroll
            for (int i = 0; i < 16; i++) {
                const float4 k4 = *(const float4*)(Ks + (g + 4*i)*PADF + d4*4);
                s[i] = fmaf(q4.x, k4.x,
                       fmaf(q4.y, k4.y,
                       fmaf(q4.z, k4.z,
                       fmaf(q4.w, k4.w, s[i]))));
            }
        }

        // ---- scale + causal mask + online softmax ----
        float mt = -1e30f;
        const bool diag = (jt == qt);
        #pragma unroll
        for (int i = 0; i < 16; i++) {
            s[i] *= 0.125f;                       // 1/sqrt(64)
            if (diag && (g + 4*i) > r) s[i] = -1e30f;
            mt = fmaxf(mt, s[i]);
        }
        mt = fmaxf(mt, __shfl_xor_sync(0xffffffffu, mt, 1));
        mt = fmaxf(mt, __shfl_xor_sync(0xffffffffu, mt, 2));
        const float m_new = fmaxf(m_run, mt);
        const float alpha = __expf(m_run - m_new);

        float psum = 0.f;
        #pragma unroll
        for (int i = 0; i < 16; i++) {
            const float p = __expf(s[i] - m_new);
            psum += p;
            Ps[r*PADF + g + 4*i] = p;
        }
        psum += __shfl_xor_sync(0xffffffffu, psum, 1);
        psum += __shfl_xor_sync(0xffffffffu, psum, 2);
        l_run = l_run * alpha + psum;
        m_run = m_new;
        #pragma unroll
        for (int i = 0; i < 16; i++) acc[i] *= alpha;

        __syncwarp();   // Ps for row r written only by this warp's 4 threads

        // ---- acc += P[r][:] @ V ----
        #pragma unroll 4
        for (int j = 0; j < QT; j++) {
            const float p = Ps[r*PADF + j];
            #pragma unroll
            for (int mI = 0; mI < 4; mI++) {
                const float4 v4 = *(const float4*)(Vs + j*PADF + (g + 4*mI)*4);
                acc[mI*4+0] = fmaf(p, v4.x, acc[mI*4+0]);
                acc[mI*4+1] = fmaf(p, v4.y, acc[mI*4+1]);
                acc[mI*4+2] = fmaf(p, v4.z, acc[mI*4+2]);
                acc[mI*4+3] = fmaf(p, v4.w, acc[mI*4+3]);
            }
        }
    }

    const float inv = 1.f / l_run;
    float* op = g_vals + base + (size_t)(q0 + r) * D_DIM;
    #pragma unroll
    for (int mI = 0; mI < 4; mI++) {
        float4 o;
        o.x = acc[mI*4+0]*inv; o.y = acc[mI*4+1]*inv;
        o.z = acc[mI*4+2]*inv; o.w = acc[mI*4+3]*inv;
        *(float4*)(op + (g + 4*mI)*4) = o;
    }
}

// ---------------------------------------------------------------------------
// kernel_launch
// inputs: x, mask, Wq, bq, Wk, bk, Wv, bv, Wo, bo   (mask ignored; causal known)
// ---------------------------------------------------------------------------
extern "C" void kernel_launch(void* const* d_in, const int* in_sizes, int n_in,
                              void* d_out, int out_size)
{
    (void)in_sizes; (void)n_in; (void)out_size;
    const float* x  = (const float*)d_in[0];
    const float* Wq = (const float*)d_in[2];
    const float* bq = (const float*)d_in[3];
    const float* Wk = (const float*)d_in[4];
    const float* bk = (const float*)d_in[5];
    const float* Wv = (const float*)d_in[6];
    const float* bv = (const float*)d_in[7];
    const float* Wo = (const float*)d_in[8];
    const float* bo = (const float*)d_in[9];
    float* out = (float*)d_out;

    float *qp, *kp, *vp, *valsp;
    cudaGetSymbolAddress((void**)&qp,    g_q);
    cudaGetSymbolAddress((void**)&kp,    g_k);
    cudaGetSymbolAddress((void**)&vp,    g_v);
    cudaGetSymbolAddress((void**)&valsp, g_vals);

    cudaFuncSetAttribute(attn_kernel,
                         cudaFuncAttributeMaxDynamicSharedMemorySize, ATTN_SMEM);

    dim3 blk(256);
    dim3 gP(D_DIM/128, NROWS/128);         // (8, 64)
    sgemm_nt_bias<<<gP, blk>>>(x, Wq, bq, qp, NROWS, D_DIM, D_DIM);
    sgemm_nt_bias<<<gP, blk>>>(x, Wk, bk, kp, NROWS, D_DIM, D_DIM);
    sgemm_nt_bias<<<gP, blk>>>(x, Wv, bv, vp, NROWS, D_DIM, D_DIM);

    dim3 gA(S_LEN/QT, B_SZ*NH);            // (32, 64)
    attn_kernel<<<gA, blk, ATTN_SMEM>>>();

    sgemm_nt_bias<<<gP, blk>>>(valsp, Wo, bo, out, NROWS, D_DIM, D_DIM);
}

// round 4
// speedup vs baseline: 1.3642x; 1.3642x over previous
#include <cuda_runtime.h>

// ---------------------------------------------------------------------------
// MultiHeadAttention, B=4 S=2048 D=1024 H=16 DK=64, fp32.
// R3: attention rewritten as two register-blocked smem GEMMs (8x4/thread),
//     Q/K transposed in smem, P exchanged via smem transposed (warp-local).
// ---------------------------------------------------------------------------

#define B_SZ   4
#define S_LEN  2048
#define D_DIM  1024
#define NH     16
#define DKH    64
#define NROWS  (B_SZ * S_LEN)          // 8192

__device__ float g_q[NROWS * D_DIM];
__device__ float g_k[NROWS * D_DIM];
__device__ float g_v[NROWS * D_DIM];
__device__ float g_vals[NROWS * D_DIM];

// ---------------------------------------------------------------------------
// SGEMM:  C = A @ W^T + bias  (unchanged from R1; ~16:1 FMA:LDS)
// ---------------------------------------------------------------------------
__global__ void __launch_bounds__(256)
sgemm_nt_bias(const float* __restrict__ A, const float* __restrict__ W,
              const float* __restrict__ bias, float* __restrict__ C,
              int M, int N, int K)
{
    __shared__ float As[8][128];
    __shared__ float Ws[8][128];

    const int tid = threadIdx.x;
    const int bm  = blockIdx.y * 128;
    const int bn  = blockIdx.x * 128;
    const int tx  = tid & 15;
    const int ty  = tid >> 4;
    const int lrow = tid >> 1;
    const int lk4  = (tid & 1) << 2;

    const float* Ap = A + (size_t)(bm + lrow) * K + lk4;
    const float* Wp = W + (size_t)(bn + lrow) * K + lk4;

    float acc[8][8];
    #pragma unroll
    for (int i = 0; i < 8; i++)
        #pragma unroll
        for (int j = 0; j < 8; j++) acc[i][j] = 0.f;

    for (int k0 = 0; k0 < K; k0 += 8) {
        float4 a4 = *(const float4*)(Ap + k0);
        float4 w4 = *(const float4*)(Wp + k0);
        As[lk4+0][lrow] = a4.x; As[lk4+1][lrow] = a4.y;
        As[lk4+2][lrow] = a4.z; As[lk4+3][lrow] = a4.w;
        Ws[lk4+0][lrow] = w4.x; Ws[lk4+1][lrow] = w4.y;
        Ws[lk4+2][lrow] = w4.z; Ws[lk4+3][lrow] = w4.w;
        __syncthreads();

        #pragma unroll
        for (int kk = 0; kk < 8; kk++) {
            float4 a0 = *(const float4*)(&As[kk][ty*8]);
            float4 a1 = *(const float4*)(&As[kk][ty*8+4]);
            float4 w0 = *(const float4*)(&Ws[kk][tx*8]);
            float4 w1 = *(const float4*)(&Ws[kk][tx*8+4]);
            float af[8] = {a0.x,a0.y,a0.z,a0.w,a1.x,a1.y,a1.z,a1.w};
            float wf[8] = {w0.x,w0.y,w0.z,w0.w,w1.x,w1.y,w1.z,w1.w};
            #pragma unroll
            for (int i = 0; i < 8; i++)
                #pragma unroll
                for (int j = 0; j < 8; j++)
                    acc[i][j] = fmaf(af[i], wf[j], acc[i][j]);
        }
        __syncthreads();
    }

    float bfrag[8];
    #pragma unroll
    for (int j = 0; j < 8; j++) bfrag[j] = bias[bn + tx*8 + j];

    #pragma unroll
    for (int i = 0; i < 8; i++) {
        const size_t row = (size_t)(bm + ty*8 + i);
        float* cp = C + row * N + bn + tx*8;
        float4 o0 = {acc[i][0]+bfrag[0], acc[i][1]+bfrag[1],
                     acc[i][2]+bfrag[2], acc[i][3]+bfrag[3]};
        float4 o1 = {acc[i][4]+bfrag[4], acc[i][5]+bfrag[5],
                     acc[i][6]+bfrag[6], acc[i][7]+bfrag[7]};
        *(float4*)cp     = o0;
        *(float4*)(cp+4) = o1;
    }
}

// ---------------------------------------------------------------------------
// Flash attention v2: tile = 128 queries x 64 keys per iteration, one (b,h).
// 256 threads = 16(tx) x 16(ty); per thread: 8 query rows (ty*8..+8) x
// 4 spread key/dk columns (tx + 16*jj).
//
// smem:
//   Qts[64 d][128 row]        stride 128 (transposed Q, loaded once)
//   Kts[64 d][64 col]         stride 64  (transposed K, per tile)
//   Vs [64 j][68]             row-major V, per tile
//   Pts[64 j][132]            transposed P (row index = query row), warp-local
// All hot-loop loads are float4-broadcasts or <=256B/warp; transpose stores
// are bank-conflict-free (row index distinct across warp, stride % 32 == 0).
// ---------------------------------------------------------------------------
#define QT 128
#define KT 64
#define ATTN_SMEM ((64*128 + 64*64 + 64*68 + 64*132) * (int)sizeof(float)) // 100352

__global__ void __launch_bounds__(256, 2)
attn_kernel()
{
    extern __shared__ float sm[];
    float* Qts = sm;                  // [64][128]
    float* Kts = Qts + 64*128;        // [64][64]
    float* Vs  = Kts + 64*64;         // [64][68]
    float* Pts = Vs  + 64*68;         // [64][132]

    const int tid = threadIdx.x;
    const int qt  = (int)gridDim.x - 1 - (int)blockIdx.x;   // big blocks first
    const int bh  = blockIdx.y;
    const size_t base = (size_t)(bh >> 4) * S_LEN * D_DIM + (size_t)(bh & 15) * DKH;
    const int q0 = qt * QT;
    const int tx = tid & 15;
    const int ty = tid >> 4;

    // ---- load Q tile transposed: Qts[d][row] ----
    for (int idx = tid; idx < 128*16; idx += 256) {
        int row = idx & 127;
        int c4  = (idx >> 7) << 2;
        float4 v = *(const float4*)(g_q + base + (size_t)(q0+row)*D_DIM + c4);
        Qts[(c4+0)*128 + row] = v.x;
        Qts[(c4+1)*128 + row] = v.y;
        Qts[(c4+2)*128 + row] = v.z;
        Qts[(c4+3)*128 + row] = v.w;
    }

    float acc[8][4];
    float m_run[8], l_run[8];
    #pragma unroll
    for (int i = 0; i < 8; i++) {
        m_run[i] = -1e30f; l_run[i] = 0.f;
        #pragma unroll
        for (int jj = 0; jj < 4; jj++) acc[i][jj] = 0.f;
    }

    const int ntiles = 2*qt + 2;
    for (int jt = 0; jt < ntiles; jt++) {
        __syncthreads();          // previous tile's PV reads done
        const int k0 = jt * KT;

        // K transposed: Kts[d][col]
        for (int idx = tid; idx < 64*16; idx += 256) {
            int row = idx & 63;
            int c4  = (idx >> 6) << 2;
            float4 v = *(const float4*)(g_k + base + (size_t)(k0+row)*D_DIM + c4);
            Kts[(c4+0)*64 + row] = v.x;
            Kts[(c4+1)*64 + row] = v.y;
            Kts[(c4+2)*64 + row] = v.z;
            Kts[(c4+3)*64 + row] = v.w;
        }
        // V row-major: Vs[j][dk]
        for (int idx = tid; idx < 64*16; idx += 256) {
            int row = idx >> 4;
            int c4  = (idx & 15) << 2;
            *(float4*)(Vs + row*68 + c4) =
                *(const float4*)(g_v + base + (size_t)(k0+row)*D_DIM + c4);
        }
        __syncthreads();

        // ---- score GEMM: s[i][jj] = Q[row] . K[col] ----
        float s[8][4];
        #pragma unroll
        for (int i = 0; i < 8; i++)
            #pragma unroll
            for (int jj = 0; jj < 4; jj++) s[i][jj] = 0.f;

        #pragma unroll 4
        for (int d = 0; d < 64; d++) {
            float4 a0 = *(const float4*)(Qts + d*128 + ty*8);
            float4 a1 = *(const float4*)(Qts + d*128 + ty*8 + 4);
            float af[8] = {a0.x,a0.y,a0.z,a0.w,a1.x,a1.y,a1.z,a1.w};
            float wf[4];
            wf[0] = Kts[d*64 + tx];
            wf[1] = Kts[d*64 + tx + 16];
            wf[2] = Kts[d*64 + tx + 32];
            wf[3] = Kts[d*64 + tx + 48];
            #pragma unroll
            for (int i = 0; i < 8; i++)
                #pragma unroll
                for (int jj = 0; jj < 4; jj++)
                    s[i][jj] = fmaf(af[i], wf[jj], s[i][jj]);
        }

        // ---- scale + causal mask + online softmax (per row, warp-uniform) ----
        const bool diag = (jt >= 2*qt);
        #pragma unroll
        for (int i = 0; i < 8; i++) {
            const int row_g = q0 + ty*8 + i;
            float mt = -1e30f;
            #pragma unroll
            for (int jj = 0; jj < 4; jj++) {
                float v = s[i][jj] * 0.125f;          // 1/sqrt(64)
                if (diag && (k0 + tx + 16*jj) > row_g) v = -1e30f;
                s[i][jj] = v;
                mt = fmaxf(mt, v);
            }
            mt = fmaxf(mt, __shfl_xor_sync(0xffffffffu, mt, 1));
            mt = fmaxf(mt, __shfl_xor_sync(0xffffffffu, mt, 2));
            mt = fmaxf(mt, __shfl_xor_sync(0xffffffffu, mt, 4));
            mt = fmaxf(mt, __shfl_xor_sync(0xffffffffu, mt, 8));

            const float m_new = fmaxf(m_run[i], mt);
            const float alpha = __expf(m_run[i] - m_new);
            m_run[i] = m_new;

            float ps = 0.f;
            #pragma unroll
            for (int jj = 0; jj < 4; jj++) {
                float p = __expf(s[i][jj] - m_new);
                s[i][jj] = p;
                ps += p;
            }
            ps += __shfl_xor_sync(0xffffffffu, ps, 1);
            ps += __shfl_xor_sync(0xffffffffu, ps, 2);
            ps += __shfl_xor_sync(0xffffffffu, ps, 4);
            ps += __shfl_xor_sync(0xffffffffu, ps, 8);
            l_run[i] = l_run[i] * alpha + ps;

            #pragma unroll
            for (int jj = 0; jj < 4; jj++) acc[i][jj] *= alpha;
        }

        // ---- write P transposed (only my warp reads my rows) ----
        __syncwarp();
        #pragma unroll
        for (int jj = 0; jj < 4; jj++) {
            float* pp = Pts + (tx + 16*jj)*132 + ty*8;
            *(float4*)pp =
                make_float4(s[0][jj], s[1][jj], s[2][jj], s[3][jj]);
            *(float4*)(pp+4) =
                make_float4(s[4][jj], s[5][jj], s[6][jj], s[7][jj]);
        }
        __syncwarp();

        // ---- PV GEMM: acc[i][jj] += sum_j P[row][j] * V[j][dk] ----
        #pragma unroll 4
        for (int j = 0; j < 64; j++) {
            float4 a0 = *(const float4*)(Pts + j*132 + ty*8);
            float4 a1 = *(const float4*)(Pts + j*132 + ty*8 + 4);
            float af[8] = {a0.x,a0.y,a0.z,a0.w,a1.x,a1.y,a1.z,a1.w};
            float wf[4];
            wf[0] = Vs[j*68 + tx];
            wf[1] = Vs[j*68 + tx + 16];
            wf[2] = Vs[j*68 + tx + 32];
            wf[3] = Vs[j*68 + tx + 48];
            #pragma unroll
            for (int i = 0; i < 8; i++)
                #pragma unroll
                for (int jj = 0; jj < 4; jj++)
                    acc[i][jj] = fmaf(af[i], wf[jj], acc[i][jj]);
        }
    }

    // ---- normalize + store ----
    #pragma unroll
    for (int i = 0; i < 8; i++) {
        const float inv = 1.f / l_run[i];
        float* op = g_vals + base + (size_t)(q0 + ty*8 + i) * D_DIM;
        #pragma unroll
        for (int jj = 0; jj < 4; jj++)
            op[tx + 16*jj] = acc[i][jj] * inv;
    }
}

// ---------------------------------------------------------------------------
extern "C" void kernel_launch(void* const* d_in, const int* in_sizes, int n_in,
                              void* d_out, int out_size)
{
    (void)in_sizes; (void)n_in; (void)out_size;
    const float* x  = (const float*)d_in[0];
    const float* Wq = (const float*)d_in[2];
    const float* bq = (const float*)d_in[3];
    const float* Wk = (const float*)d_in[4];
    const float* bk = (const float*)d_in[5];
    const float* Wv = (const float*)d_in[6];
    const float* bv = (const float*)d_in[7];
    const float* Wo = (const float*)d_in[8];
    const float* bo = (const float*)d_in[9];
    float* out = (float*)d_out;

    float *qp, *kp, *vp, *valsp;
    cudaGetSymbolAddress((void**)&qp,    g_q);
    cudaGetSymbolAddress((void**)&kp,    g_k);
    cudaGetSymbolAddress((void**)&vp,    g_v);
    cudaGetSymbolAddress((void**)&valsp, g_vals);

    cudaFuncSetAttribute(attn_kernel,
                         cudaFuncAttributeMaxDynamicSharedMemorySize, ATTN_SMEM);

    dim3 blk(256);
    dim3 gP(D_DIM/128, NROWS/128);         // (8, 64)
    sgemm_nt_bias<<<gP, blk>>>(x, Wq, bq, qp, NROWS, D_DIM, D_DIM);
    sgemm_nt_bias<<<gP, blk>>>(x, Wk, bk, kp, NROWS, D_DIM, D_DIM);
    sgemm_nt_bias<<<gP, blk>>>(x, Wv, bv, vp, NROWS, D_DIM, D_DIM);

    dim3 gA(S_LEN/QT, B_SZ*NH);            // (16, 64)
    attn_kernel<<<gA, blk, ATTN_SMEM>>>();

    sgemm_nt_bias<<<gP, blk>>>(valsp, Wo, bo, out, NROWS, D_DIM, D_DIM);
}

// round 6
// speedup vs baseline: 2.0810x; 1.5255x over previous
#include <cuda_runtime.h>
#include <cuda_bf16.h>
#include <cstdint>

// ---------------------------------------------------------------------------
// MultiHeadAttention, B=4 S=2048 D=1024 H=16 DK=64, fp32.
// R5: tcgen05 unavailable (harness targets plain sm_100). Projections use
//     legacy tensor-core mma.sync.m16n8k16 bf16 with 3-term split:
//       C = Ah@Wh^T + Ah@Wl^T + Al@Wh^T + bias   (fp32 accum)
//     Attention kernel = R3 FFMA flash attention (unchanged).
// ---------------------------------------------------------------------------

#define B_SZ   4
#define S_LEN  2048
#define D_DIM  1024
#define NH     16
#define DKH    64
#define NROWS  (B_SZ * S_LEN)          // 8192

// fp32 scratch
__device__ float g_q[NROWS * D_DIM];
__device__ float g_k[NROWS * D_DIM];
__device__ float g_v[NROWS * D_DIM];
__device__ float g_vals[NROWS * D_DIM];
// bf16 split scratch
__device__ __nv_bfloat16 g_xh[NROWS * D_DIM];
__device__ __nv_bfloat16 g_xl[NROWS * D_DIM];
__device__ __nv_bfloat16 g_vh[NROWS * D_DIM];
__device__ __nv_bfloat16 g_vl[NROWS * D_DIM];
__device__ __nv_bfloat16 g_wh[4][D_DIM * D_DIM];   // q,k,v,o
__device__ __nv_bfloat16 g_wl[4][D_DIM * D_DIM];

// ---------------------------------------------------------------------------
// helpers
// ---------------------------------------------------------------------------
__device__ __forceinline__ uint32_t smem_u32(const void* p) {
    uint32_t a;
    asm("{ .reg .u64 t; cvta.to.shared.u64 t, %1; cvt.u32.u64 %0, t; }"
        : "=r"(a) : "l"(p));
    return a;
}
__device__ __forceinline__ void ldsm_x4(uint32_t* r, uint32_t addr) {
    asm volatile("ldmatrix.sync.aligned.m8n8.x4.shared.b16 {%0,%1,%2,%3}, [%4];"
                 : "=r"(r[0]), "=r"(r[1]), "=r"(r[2]), "=r"(r[3]) : "r"(addr));
}
__device__ __forceinline__ void mma_bf16(float* c, const uint32_t* a,
                                         uint32_t b0, uint32_t b1) {
    asm volatile("mma.sync.aligned.m16n8k16.row.col.f32.bf16.bf16.f32 "
                 "{%0,%1,%2,%3}, {%4,%5,%6,%7}, {%8,%9}, {%0,%1,%2,%3};"
                 : "+f"(c[0]), "+f"(c[1]), "+f"(c[2]), "+f"(c[3])
                 : "r"(a[0]), "r"(a[1]), "r"(a[2]), "r"(a[3]), "r"(b0), "r"(b1));
}

// ---------------------------------------------------------------------------
// split: fp32 -> bf16 hi + bf16 residual
// ---------------------------------------------------------------------------
__global__ void __launch_bounds__(256)
split_kernel(const float* __restrict__ in, __nv_bfloat16* __restrict__ hi,
             __nv_bfloat16* __restrict__ lo, int n4)
{
    int i = blockIdx.x * blockDim.x + threadIdx.x;
    if (i >= n4) return;
    float4 v = ((const float4*)in)[i];
    __nv_bfloat16 h0 = __float2bfloat16(v.x);
    __nv_bfloat16 h1 = __float2bfloat16(v.y);
    __nv_bfloat16 h2 = __float2bfloat16(v.z);
    __nv_bfloat16 h3 = __float2bfloat16(v.w);
    __nv_bfloat16 l0 = __float2bfloat16(v.x - __bfloat162float(h0));
    __nv_bfloat16 l1 = __float2bfloat16(v.y - __bfloat162float(h1));
    __nv_bfloat16 l2 = __float2bfloat16(v.z - __bfloat162float(h2));
    __nv_bfloat16 l3 = __float2bfloat16(v.w - __bfloat162float(h3));
    __nv_bfloat162* hp = (__nv_bfloat162*)hi;
    __nv_bfloat162* lp = (__nv_bfloat162*)lo;
    hp[2*i]   = __halves2bfloat162(h0, h1);
    hp[2*i+1] = __halves2bfloat162(h2, h3);
    lp[2*i]   = __halves2bfloat162(l0, l1);
    lp[2*i+1] = __halves2bfloat162(l2, l3);
}

// ---------------------------------------------------------------------------
// HMMA GEMM:  C[M,N] = Ah@Wh^T + Ah@Wl^T + Al@Wh^T + bias
// A*: [M,1024] bf16 K-major.  W*: [N,1024] bf16 K-major.  C fp32 row-major.
// CTA 128x128, warps 2(m)x4(n), warp tile 64x32, BK=32 (2 k-steps of 16).
// smem stride 40 bf16 (80B) -> ldmatrix 8-row phases hit all 32 banks once.
// ---------------------------------------------------------------------------
#define BK     32
#define SSTR   40                      // bf16 stride per row
#define GK     1024

__global__ void __launch_bounds__(256)
gemm_bf16x3(const __nv_bfloat16* __restrict__ Ah, const __nv_bfloat16* __restrict__ Al,
            const __nv_bfloat16* __restrict__ Wh, const __nv_bfloat16* __restrict__ Wl,
            const float* __restrict__ bias, float* __restrict__ C, int N)
{
    __shared__ __align__(16) __nv_bfloat16 sAh[128 * SSTR];
    __shared__ __align__(16) __nv_bfloat16 sAl[128 * SSTR];
    __shared__ __align__(16) __nv_bfloat16 sWh[128 * SSTR];
    __shared__ __align__(16) __nv_bfloat16 sWl[128 * SSTR];

    const int tid = threadIdx.x;
    const int wid = tid >> 5;
    const int L   = tid & 31;
    const int wm  = wid >> 2;          // 0..1
    const int wn  = wid & 3;           // 0..3
    const int bn  = blockIdx.x * 128;
    const int bm  = blockIdx.y * 128;

    const uint32_t sAh_b = smem_u32(sAh);
    const uint32_t sAl_b = smem_u32(sAl);
    const uint32_t sWh_b = smem_u32(sWh);
    const uint32_t sWl_b = smem_u32(sWl);

    // per-lane ldmatrix byte offsets (within a tile), before +kk*2
    uint32_t aoff[4];
    #pragma unroll
    for (int mf = 0; mf < 4; mf++)
        aoff[mf] = (uint32_t)(((wm*64 + mf*16 + (L & 15)) * SSTR + ((L >> 4) << 3)) * 2);
    uint32_t boff[2];
    #pragma unroll
    for (int nfp = 0; nfp < 2; nfp++)
        boff[nfp] = (uint32_t)(((wn*32 + nfp*16 + (L & 7) + ((L >> 4) << 3)) * SSTR
                                + (((L >> 3) & 1) << 3)) * 2);

    float acc[4][4][4];                // [mf][nf][reg]
    #pragma unroll
    for (int mf = 0; mf < 4; mf++)
        #pragma unroll
        for (int nf = 0; nf < 4; nf++)
            #pragma unroll
            for (int r = 0; r < 4; r++) acc[mf][nf][r] = 0.f;

    const int lrow = tid >> 1;
    const int lcolA = (tid & 1) * 16;  // bf16 col base (two uint4 each)

    for (int k0 = 0; k0 < GK; k0 += BK) {
        // ---- load 4 tiles (128 x 32 bf16 each) ----
        #pragma unroll
        for (int j = 0; j < 2; j++) {
            const int col = lcolA + j*8;
            const size_t go = (size_t)lrow * GK + k0 + col;
            const uint32_t so = (uint32_t)(lrow * SSTR + col) * 2;
            *(uint4*)((char*)sAh + so) = *(const uint4*)(Ah + (size_t)bm * GK + go);
            *(uint4*)((char*)sAl + so) = *(const uint4*)(Al + (size_t)bm * GK + go);
            *(uint4*)((char*)sWh + so) = *(const uint4*)(Wh + (size_t)bn * GK + go);
            *(uint4*)((char*)sWl + so) = *(const uint4*)(Wl + (size_t)bn * GK + go);
        }
        __syncthreads();

        #pragma unroll
        for (int kk = 0; kk < BK; kk += 16) {
            const uint32_t kb = (uint32_t)(kk * 2);
            uint32_t af[4][4], bh[2][4], bl[2][4];

            #pragma unroll
            for (int mf = 0; mf < 4; mf++) ldsm_x4(af[mf], sAh_b + aoff[mf] + kb);
            #pragma unroll
            for (int p = 0; p < 2; p++) {
                ldsm_x4(bh[p], sWh_b + boff[p] + kb);
                ldsm_x4(bl[p], sWl_b + boff[p] + kb);
            }

            // Ah*Wh and Ah*Wl
            #pragma unroll
            for (int mf = 0; mf < 4; mf++)
                #pragma unroll
                for (int nf = 0; nf < 4; nf++) {
                    const int p = nf >> 1, h = (nf & 1) << 1;
                    mma_bf16(acc[mf][nf], af[mf], bh[p][h], bh[p][h+1]);
                    mma_bf16(acc[mf][nf], af[mf], bl[p][h], bl[p][h+1]);
                }
            // Al*Wh
            #pragma unroll
            for (int mf = 0; mf < 4; mf++) ldsm_x4(af[mf], sAl_b + aoff[mf] + kb);
            #pragma unroll
            for (int mf = 0; mf < 4; mf++)
                #pragma unroll
                for (int nf = 0; nf < 4; nf++) {
                    const int p = nf >> 1, h = (nf & 1) << 1;
                    mma_bf16(acc[mf][nf], af[mf], bh[p][h], bh[p][h+1]);
                }
        }
        __syncthreads();
    }

    // ---- epilogue: bias + store ----
    #pragma unroll
    for (int mf = 0; mf < 4; mf++) {
        const int row0 = bm + wm*64 + mf*16 + (L >> 2);
        #pragma unroll
        for (int nf = 0; nf < 4; nf++) {
            const int col = bn + wn*32 + nf*8 + ((L & 3) << 1);
            const float b0 = bias[col], b1 = bias[col + 1];
            float2 v0 = {acc[mf][nf][0] + b0, acc[mf][nf][1] + b1};
            float2 v1 = {acc[mf][nf][2] + b0, acc[mf][nf][3] + b1};
            *(float2*)(C + (size_t)row0 * N + col)       = v0;
            *(float2*)(C + (size_t)(row0 + 8) * N + col) = v1;
        }
    }
}

// ---------------------------------------------------------------------------
// Flash attention (R3, unchanged): tile 128q x 64k, 8x4/thread GEMMs.
// ---------------------------------------------------------------------------
#define QT 128
#define KT 64
#define ATTN_SMEM ((64*128 + 64*64 + 64*68 + 64*132) * (int)sizeof(float)) // 100352

__global__ void __launch_bounds__(256, 2)
attn_kernel()
{
    extern __shared__ float smf[];
    float* Qts = smf;                 // [64][128]
    float* Kts = Qts + 64*128;        // [64][64]
    float* Vs  = Kts + 64*64;         // [64][68]
    float* Pts = Vs  + 64*68;         // [64][132]

    const int tid = threadIdx.x;
    const int qt  = (int)gridDim.x - 1 - (int)blockIdx.x;
    const int bh  = blockIdx.y;
    const size_t base = (size_t)(bh >> 4) * S_LEN * D_DIM + (size_t)(bh & 15) * DKH;
    const int q0 = qt * QT;
    const int tx = tid & 15;
    const int ty = tid >> 4;

    for (int idx = tid; idx < 128*16; idx += 256) {
        int row = idx & 127;
        int c4  = (idx >> 7) << 2;
        float4 v = *(const float4*)(g_q + base + (size_t)(q0+row)*D_DIM + c4);
        Qts[(c4+0)*128 + row] = v.x;
        Qts[(c4+1)*128 + row] = v.y;
        Qts[(c4+2)*128 + row] = v.z;
        Qts[(c4+3)*128 + row] = v.w;
    }

    float acc[8][4];
    float m_run[8], l_run[8];
    #pragma unroll
    for (int i = 0; i < 8; i++) {
        m_run[i] = -1e30f; l_run[i] = 0.f;
        #pragma unroll
        for (int jj = 0; jj < 4; jj++) acc[i][jj] = 0.f;
    }

    const int ntiles = 2*qt + 2;
    for (int jt = 0; jt < ntiles; jt++) {
        __syncthreads();
        const int k0 = jt * KT;

        for (int idx = tid; idx < 64*16; idx += 256) {
            int row = idx & 63;
            int c4  = (idx >> 6) << 2;
            float4 v = *(const float4*)(g_k + base + (size_t)(k0+row)*D_DIM + c4);
            Kts[(c4+0)*64 + row] = v.x;
            Kts[(c4+1)*64 + row] = v.y;
            Kts[(c4+2)*64 + row] = v.z;
            Kts[(c4+3)*64 + row] = v.w;
        }
        for (int idx = tid; idx < 64*16; idx += 256) {
            int row = idx >> 4;
            int c4  = (idx & 15) << 2;
            *(float4*)(Vs + row*68 + c4) =
                *(const float4*)(g_v + base + (size_t)(k0+row)*D_DIM + c4);
        }
        __syncthreads();

        float s[8][4];
        #pragma unroll
        for (int i = 0; i < 8; i++)
            #pragma unroll
            for (int jj = 0; jj < 4; jj++) s[i][jj] = 0.f;

        #pragma unroll 4
        for (int d = 0; d < 64; d++) {
            float4 a0 = *(const float4*)(Qts + d*128 + ty*8);
            float4 a1 = *(const float4*)(Qts + d*128 + ty*8 + 4);
            float af[8] = {a0.x,a0.y,a0.z,a0.w,a1.x,a1.y,a1.z,a1.w};
            float wf[4];
            wf[0] = Kts[d*64 + tx];
            wf[1] = Kts[d*64 + tx + 16];
            wf[2] = Kts[d*64 + tx + 32];
            wf[3] = Kts[d*64 + tx + 48];
            #pragma unroll
            for (int i = 0; i < 8; i++)
                #pragma unroll
                for (int jj = 0; jj < 4; jj++)
                    s[i][jj] = fmaf(af[i], wf[jj], s[i][jj]);
        }

        const bool diag = (jt >= 2*qt);
        #pragma unroll
        for (int i = 0; i < 8; i++) {
            const int row_g = q0 + ty*8 + i;
            float mt = -1e30f;
            #pragma unroll
            for (int jj = 0; jj < 4; jj++) {
                float v = s[i][jj] * 0.125f;
                if (diag && (k0 + tx + 16*jj) > row_g) v = -1e30f;
                s[i][jj] = v;
                mt = fmaxf(mt, v);
            }
            mt = fmaxf(mt, __shfl_xor_sync(0xffffffffu, mt, 1));
            mt = fmaxf(mt, __shfl_xor_sync(0xffffffffu, mt, 2));
            mt = fmaxf(mt, __shfl_xor_sync(0xffffffffu, mt, 4));
            mt = fmaxf(mt, __shfl_xor_sync(0xffffffffu, mt, 8));

            const float m_new = fmaxf(m_run[i], mt);
            const float alpha = __expf(m_run[i] - m_new);
            m_run[i] = m_new;

            float ps = 0.f;
            #pragma unroll
            for (int jj = 0; jj < 4; jj++) {
                float p = __expf(s[i][jj] - m_new);
                s[i][jj] = p;
                ps += p;
            }
            ps += __shfl_xor_sync(0xffffffffu, ps, 1);
            ps += __shfl_xor_sync(0xffffffffu, ps, 2);
            ps += __shfl_xor_sync(0xffffffffu, ps, 4);
            ps += __shfl_xor_sync(0xffffffffu, ps, 8);
            l_run[i] = l_run[i] * alpha + ps;

            #pragma unroll
            for (int jj = 0; jj < 4; jj++) acc[i][jj] *= alpha;
        }

        __syncwarp();
        #pragma unroll
        for (int jj = 0; jj < 4; jj++) {
            float* pp = Pts + (tx + 16*jj)*132 + ty*8;
            *(float4*)pp     = make_float4(s[0][jj], s[1][jj], s[2][jj], s[3][jj]);
            *(float4*)(pp+4) = make_float4(s[4][jj], s[5][jj], s[6][jj], s[7][jj]);
        }
        __syncwarp();

        #pragma unroll 4
        for (int j = 0; j < 64; j++) {
            float4 a0 = *(const float4*)(Pts + j*132 + ty*8);
            float4 a1 = *(const float4*)(Pts + j*132 + ty*8 + 4);
            float af[8] = {a0.x,a0.y,a0.z,a0.w,a1.x,a1.y,a1.z,a1.w};
            float wf[4];
            wf[0] = Vs[j*68 + tx];
            wf[1] = Vs[j*68 + tx + 16];
            wf[2] = Vs[j*68 + tx + 32];
            wf[3] = Vs[j*68 + tx + 48];
            #pragma unroll
            for (int i = 0; i < 8; i++)
                #pragma unroll
                for (int jj = 0; jj < 4; jj++)
                    acc[i][jj] = fmaf(af[i], wf[jj], acc[i][jj]);
        }
    }

    #pragma unroll
    for (int i = 0; i < 8; i++) {
        const float inv = 1.f / l_run[i];
        float* op = g_vals + base + (size_t)(q0 + ty*8 + i) * D_DIM;
        #pragma unroll
        for (int jj = 0; jj < 4; jj++)
            op[tx + 16*jj] = acc[i][jj] * inv;
    }
}

// ---------------------------------------------------------------------------
extern "C" void kernel_launch(void* const* d_in, const int* in_sizes, int n_in,
                              void* d_out, int out_size)
{
    (void)in_sizes; (void)n_in; (void)out_size;
    const float* x  = (const float*)d_in[0];
    const float* Wq = (const float*)d_in[2];
    const float* bq = (const float*)d_in[3];
    const float* Wk = (const float*)d_in[4];
    const float* bk = (const float*)d_in[5];
    const float* Wv = (const float*)d_in[6];
    const float* bv = (const float*)d_in[7];
    const float* Wo = (const float*)d_in[8];
    const float* bo = (const float*)d_in[9];
    float* out = (float*)d_out;

    float *qp, *kp, *vp, *valsp;
    __nv_bfloat16 *xh, *xl, *vh, *vl, *wh, *wl;
    cudaGetSymbolAddress((void**)&qp,    g_q);
    cudaGetSymbolAddress((void**)&kp,    g_k);
    cudaGetSymbolAddress((void**)&vp,    g_v);
    cudaGetSymbolAddress((void**)&valsp, g_vals);
    cudaGetSymbolAddress((void**)&xh,    g_xh);
    cudaGetSymbolAddress((void**)&xl,    g_xl);
    cudaGetSymbolAddress((void**)&vh,    g_vh);
    cudaGetSymbolAddress((void**)&vl,    g_vl);
    cudaGetSymbolAddress((void**)&wh,    g_wh);
    cudaGetSymbolAddress((void**)&wl,    g_wl);

    cudaFuncSetAttribute(attn_kernel,
                         cudaFuncAttributeMaxDynamicSharedMemorySize, ATTN_SMEM);

    const int WSZ = D_DIM * D_DIM;
    const int XN4 = (NROWS * D_DIM) / 4;
    const int WN4 = WSZ / 4;

    dim3 blk(256);

    // splits
    split_kernel<<<(XN4 + 255) / 256, blk>>>(x,  xh, xl, XN4);
    split_kernel<<<(WN4 + 255) / 256, blk>>>(Wq, wh + 0*WSZ, wl + 0*WSZ, WN4);
    split_kernel<<<(WN4 + 255) / 256, blk>>>(Wk, wh + 1*WSZ, wl + 1*WSZ, WN4);
    split_kernel<<<(WN4 + 255) / 256, blk>>>(Wv, wh + 2*WSZ, wl + 2*WSZ, WN4);
    split_kernel<<<(WN4 + 255) / 256, blk>>>(Wo, wh + 3*WSZ, wl + 3*WSZ, WN4);

    // projections on tensor cores (HMMA)
    dim3 gG(D_DIM / 128, NROWS / 128);      // (8, 64)
    gemm_bf16x3<<<gG, blk>>>(xh, xl, wh + 0*WSZ, wl + 0*WSZ, bq, qp, D_DIM);
    gemm_bf16x3<<<gG, blk>>>(xh, xl, wh + 1*WSZ, wl + 1*WSZ, bk, kp, D_DIM);
    gemm_bf16x3<<<gG, blk>>>(xh, xl, wh + 2*WSZ, wl + 2*WSZ, bv, vp, D_DIM);

    // attention
    dim3 gA(S_LEN / QT, B_SZ * NH);         // (16, 64)
    attn_kernel<<<gA, blk, ATTN_SMEM>>>();

    // output projection
    split_kernel<<<(XN4 + 255) / 256, blk>>>(valsp, vh, vl, XN4);
    gemm_bf16x3<<<gG, blk>>>(vh, vl, wh + 3*WSZ, wl + 3*WSZ, bo, out, D_DIM);
}

// round 7
// speedup vs baseline: 2.9856x; 1.4347x over previous
#include <cuda_runtime.h>
#include <cuda_bf16.h>
#include <cstdint>

// ---------------------------------------------------------------------------
// MultiHeadAttention, B=4 S=2048 D=1024 H=16 DK=64, fp32.
// R6: full tensor-core pipeline (legacy mma.sync bf16, 3-term split):
//   - projections: HMMA GEMM, epilogue writes bf16 hi/lo split directly
//     (Q prescaled by 1/sqrt(DK)=0.125)
//   - attention: HMMA flash attention, Q frags register-resident,
//     P permuted in registers to A-frags, V via ldmatrix.trans,
//     polynomial exp on the FMA pipe (no MUFU bottleneck)
//   - output projection: HMMA GEMM, fp32 out
// ---------------------------------------------------------------------------

#define B_SZ   4
#define S_LEN  2048
#define D_DIM  1024
#define NH     16
#define DKH    64
#define NROWS  (B_SZ * S_LEN)          // 8192

// bf16 split scratch
__device__ __nv_bfloat16 g_xh[NROWS * D_DIM];
__device__ __nv_bfloat16 g_xl[NROWS * D_DIM];
__device__ __nv_bfloat16 g_wh[4][D_DIM * D_DIM];   // q,k,v,o
__device__ __nv_bfloat16 g_wl[4][D_DIM * D_DIM];
__device__ __nv_bfloat16 g_qh[NROWS * D_DIM];
__device__ __nv_bfloat16 g_ql[NROWS * D_DIM];
__device__ __nv_bfloat16 g_kh[NROWS * D_DIM];
__device__ __nv_bfloat16 g_kl[NROWS * D_DIM];
__device__ __nv_bfloat16 g_vh[NROWS * D_DIM];
__device__ __nv_bfloat16 g_vl[NROWS * D_DIM];
__device__ __nv_bfloat16 g_oh[NROWS * D_DIM];
__device__ __nv_bfloat16 g_ol[NROWS * D_DIM];

// ---------------------------------------------------------------------------
// helpers
// ---------------------------------------------------------------------------
__device__ __forceinline__ uint32_t smem_u32(const void* p) {
    uint32_t a;
    asm("{ .reg .u64 t; cvta.to.shared.u64 t, %1; cvt.u32.u64 %0, t; }"
        : "=r"(a) : "l"(p));
    return a;
}
__device__ __forceinline__ void ldsm_x4(uint32_t* r, uint32_t addr) {
    asm volatile("ldmatrix.sync.aligned.m8n8.x4.shared.b16 {%0,%1,%2,%3}, [%4];"
                 : "=r"(r[0]), "=r"(r[1]), "=r"(r[2]), "=r"(r[3]) : "r"(addr));
}
__device__ __forceinline__ void ldsm_x4_t(uint32_t* r, uint32_t addr) {
    asm volatile("ldmatrix.sync.aligned.m8n8.x4.trans.shared.b16 {%0,%1,%2,%3}, [%4];"
                 : "=r"(r[0]), "=r"(r[1]), "=r"(r[2]), "=r"(r[3]) : "r"(addr));
}
__device__ __forceinline__ void mma_bf16(float* c, const uint32_t* a,
                                         uint32_t b0, uint32_t b1) {
    asm volatile("mma.sync.aligned.m16n8k16.row.col.f32.bf16.bf16.f32 "
                 "{%0,%1,%2,%3}, {%4,%5,%6,%7}, {%8,%9}, {%0,%1,%2,%3};"
                 : "+f"(c[0]), "+f"(c[1]), "+f"(c[2]), "+f"(c[3])
                 : "r"(a[0]), "r"(a[1]), "r"(a[2]), "r"(a[3]), "r"(b0), "r"(b1));
}
// pack two floats -> bf16x2 (lo in low 16 bits)
__device__ __forceinline__ uint32_t packbf(float lo, float hi) {
    uint32_t r;
    asm("cvt.rn.bf16x2.f32 %0, %1, %2;" : "=r"(r) : "f"(hi), "f"(lo));
    return r;
}
// split pair into hi bf16x2 + residual bf16x2
__device__ __forceinline__ void split2(float lo, float hi, uint32_t& h, uint32_t& l) {
    h = packbf(lo, hi);
    float hlo = __uint_as_float(h << 16);
    float hhi = __uint_as_float(h & 0xFFFF0000u);
    l = packbf(lo - hlo, hi - hhi);
}
// fast exp on FMA pipe: exp(x), x <= ~0, clamped below at 2^-126
__device__ __forceinline__ float exp_fast(float x) {
    float y = x * 1.4426950408889634f;
    y = fmaxf(y, -126.0f);
    float t = y + 12582912.0f;           // round-to-nearest int via 1.5*2^23
    float n = t - 12582912.0f;
    float r = y - n;
    float p = 1.3333558146e-3f;
    p = fmaf(p, r, 9.6181291076e-3f);
    p = fmaf(p, r, 5.5504108664e-2f);
    p = fmaf(p, r, 2.4022650696e-1f);
    p = fmaf(p, r, 6.9314718056e-1f);
    p = fmaf(p, r, 1.0f);
    int e = (__float_as_int(t) - 0x4B400000 + 127) << 23;
    return p * __int_as_float(e);
}

// ---------------------------------------------------------------------------
// split: fp32 -> bf16 hi + bf16 residual (for x and the weights)
// ---------------------------------------------------------------------------
__global__ void __launch_bounds__(256)
split_kernel(const float* __restrict__ in, __nv_bfloat16* __restrict__ hi,
             __nv_bfloat16* __restrict__ lo, int n4)
{
    int i = blockIdx.x * blockDim.x + threadIdx.x;
    if (i >= n4) return;
    float4 v = ((const float4*)in)[i];
    uint32_t h0, l0, h1, l1;
    split2(v.x, v.y, h0, l0);
    split2(v.z, v.w, h1, l1);
    uint2 hh = {h0, h1}, ll = {l0, l1};
    ((uint2*)hi)[i] = hh;
    ((uint2*)lo)[i] = ll;
}

// ---------------------------------------------------------------------------
// HMMA GEMM:  C = (A@W^T + bias) * scale
// OUT_MODE 0: fp32 C.  OUT_MODE 1: bf16 split (Ch hi, Cl residual).
// CTA 128x128, warps 2(m)x4(n), warp tile 64x32, BK=32.
// ---------------------------------------------------------------------------
#define BK     32
#define SSTR   40
#define GK     1024

template<int OUT_MODE>
__global__ void __launch_bounds__(256)
gemm_bf16x3(const __nv_bfloat16* __restrict__ Ah, const __nv_bfloat16* __restrict__ Al,
            const __nv_bfloat16* __restrict__ Wh, const __nv_bfloat16* __restrict__ Wl,
            const float* __restrict__ bias, float scale,
            float* __restrict__ Cf, __nv_bfloat16* __restrict__ Ch,
            __nv_bfloat16* __restrict__ Cl, int N)
{
    __shared__ __align__(16) __nv_bfloat16 sAh[128 * SSTR];
    __shared__ __align__(16) __nv_bfloat16 sAl[128 * SSTR];
    __shared__ __align__(16) __nv_bfloat16 sWh[128 * SSTR];
    __shared__ __align__(16) __nv_bfloat16 sWl[128 * SSTR];

    const int tid = threadIdx.x;
    const int wid = tid >> 5;
    const int L   = tid & 31;
    const int wm  = wid >> 2;
    const int wn  = wid & 3;
    const int bn  = blockIdx.x * 128;
    const int bm  = blockIdx.y * 128;

    const uint32_t sAh_b = smem_u32(sAh);
    const uint32_t sAl_b = smem_u32(sAl);
    const uint32_t sWh_b = smem_u32(sWh);
    const uint32_t sWl_b = smem_u32(sWl);

    uint32_t aoff[4];
    #pragma unroll
    for (int mf = 0; mf < 4; mf++)
        aoff[mf] = (uint32_t)(((wm*64 + mf*16 + (L & 15)) * SSTR + ((L >> 4) << 3)) * 2);
    uint32_t boff[2];
    #pragma unroll
    for (int p = 0; p < 2; p++)
        boff[p] = (uint32_t)(((wn*32 + p*16 + (L & 7) + ((L >> 4) << 3)) * SSTR
                              + (((L >> 3) & 1) << 3)) * 2);

    float acc[4][4][4];
    #pragma unroll
    for (int mf = 0; mf < 4; mf++)
        #pragma unroll
        for (int nf = 0; nf < 4; nf++)
            #pragma unroll
            for (int r = 0; r < 4; r++) acc[mf][nf][r] = 0.f;

    const int lrow = tid >> 1;
    const int lcolA = (tid & 1) * 16;

    for (int k0 = 0; k0 < GK; k0 += BK) {
        #pragma unroll
        for (int j = 0; j < 2; j++) {
            const int col = lcolA + j*8;
            const size_t go = (size_t)lrow * GK + k0 + col;
            const uint32_t so = (uint32_t)(lrow * SSTR + col) * 2;
            *(uint4*)((char*)sAh + so) = *(const uint4*)(Ah + (size_t)bm * GK + go);
            *(uint4*)((char*)sAl + so) = *(const uint4*)(Al + (size_t)bm * GK + go);
            *(uint4*)((char*)sWh + so) = *(const uint4*)(Wh + (size_t)bn * GK + go);
            *(uint4*)((char*)sWl + so) = *(const uint4*)(Wl + (size_t)bn * GK + go);
        }
        __syncthreads();

        #pragma unroll
        for (int kk = 0; kk < BK; kk += 16) {
            const uint32_t kb = (uint32_t)(kk * 2);
            uint32_t af[4][4], bh[2][4], bl[2][4];
            #pragma unroll
            for (int mf = 0; mf < 4; mf++) ldsm_x4(af[mf], sAh_b + aoff[mf] + kb);
            #pragma unroll
            for (int p = 0; p < 2; p++) {
                ldsm_x4(bh[p], sWh_b + boff[p] + kb);
                ldsm_x4(bl[p], sWl_b + boff[p] + kb);
            }
            #pragma unroll
            for (int mf = 0; mf < 4; mf++)
                #pragma unroll
                for (int nf = 0; nf < 4; nf++) {
                    const int p = nf >> 1, h = (nf & 1) << 1;
                    mma_bf16(acc[mf][nf], af[mf], bh[p][h], bh[p][h+1]);
                    mma_bf16(acc[mf][nf], af[mf], bl[p][h], bl[p][h+1]);
                }
            #pragma unroll
            for (int mf = 0; mf < 4; mf++) ldsm_x4(af[mf], sAl_b + aoff[mf] + kb);
            #pragma unroll
            for (int mf = 0; mf < 4; mf++)
                #pragma unroll
                for (int nf = 0; nf < 4; nf++) {
                    const int p = nf >> 1, h = (nf & 1) << 1;
                    mma_bf16(acc[mf][nf], af[mf], bh[p][h], bh[p][h+1]);
                }
        }
        __syncthreads();
    }

    #pragma unroll
    for (int mf = 0; mf < 4; mf++) {
        const int row0 = bm + wm*64 + mf*16 + (L >> 2);
        #pragma unroll
        for (int nf = 0; nf < 4; nf++) {
            const int col = bn + wn*32 + nf*8 + ((L & 3) << 1);
            const float b0 = bias[col], b1 = bias[col + 1];
            float v00 = (acc[mf][nf][0] + b0) * scale;
            float v01 = (acc[mf][nf][1] + b1) * scale;
            float v10 = (acc[mf][nf][2] + b0) * scale;
            float v11 = (acc[mf][nf][3] + b1) * scale;
            if (OUT_MODE == 0) {
                float2 a0 = {v00, v01}, a1 = {v10, v11};
                *(float2*)(Cf + (size_t)row0 * N + col)       = a0;
                *(float2*)(Cf + (size_t)(row0 + 8) * N + col) = a1;
            } else {
                uint32_t h, l;
                split2(v00, v01, h, l);
                *(uint32_t*)(Ch + (size_t)row0 * N + col) = h;
                *(uint32_t*)(Cl + (size_t)row0 * N + col) = l;
                split2(v10, v11, h, l);
                *(uint32_t*)(Ch + (size_t)(row0 + 8) * N + col) = h;
                *(uint32_t*)(Cl + (size_t)(row0 + 8) * N + col) = l;
            }
        }
    }
}

// ---------------------------------------------------------------------------
// HMMA flash attention, causal.  CTA = 128 queries x one (b,h), 8 warps,
// warp w owns rows 16w..16w+15.  Key tile KT=64 per iteration.
//  - Q frags (Qh,Ql) register-resident across all tiles
//  - S = Qh*Kh + Qh*Kl + Ql*Kh  (bf16x3, fp32 accum; Q prescaled by 0.125)
//  - softmax with polynomial exp, P split in registers to Ph/Pl A-frags
//  - O += Ph*Vh + Ph*Vl + Pl*Vh  (V B-frags via ldmatrix.x4.trans)
//  - output written as bf16 hi/lo split (feeds final projection directly)
// smem stride 72 bf16 (144B) -> all ldmatrix phases conflict-free.
// ---------------------------------------------------------------------------
#define AST 72
#define ATTN_SMEM ((2*128 + 4*64) * AST * 2)   // 73728 B

__global__ void __launch_bounds__(256)
attn_mma()
{
    extern __shared__ __nv_bfloat16 smb[];
    __nv_bfloat16* sQh = smb;
    __nv_bfloat16* sQl = sQh + 128*AST;
    __nv_bfloat16* sKh = sQl + 128*AST;
    __nv_bfloat16* sKl = sKh + 64*AST;
    __nv_bfloat16* sVh = sKl + 64*AST;
    __nv_bfloat16* sVl = sVh + 64*AST;

    const int tid = threadIdx.x;
    const int wid = tid >> 5;
    const int L   = tid & 31;
    const int qt  = (int)gridDim.x - 1 - (int)blockIdx.x;
    const int bh  = blockIdx.y;
    const size_t base = (size_t)(bh >> 4) * S_LEN * D_DIM + (size_t)(bh & 15) * DKH;
    const int q0 = qt * 128;

    const uint32_t sQh_b = smem_u32(sQh);
    const uint32_t sQl_b = smem_u32(sQl);
    const uint32_t sKh_b = smem_u32(sKh);
    const uint32_t sKl_b = smem_u32(sKl);
    const uint32_t sVh_b = smem_u32(sVh);
    const uint32_t sVl_b = smem_u32(sVl);

    // ---- load Q tile (both splits) ----
    for (int idx = tid; idx < 1024; idx += 256) {
        const int row = idx >> 3;
        const int c8  = (idx & 7) << 3;
        const size_t go = base + (size_t)(q0 + row) * D_DIM + c8;
        *(uint4*)(sQh + row*AST + c8) = *(const uint4*)(g_qh + go);
        *(uint4*)(sQl + row*AST + c8) = *(const uint4*)(g_ql + go);
    }
    __syncthreads();

    // ---- Q fragments (held for whole kernel) ----
    uint32_t qh[4][4], ql[4][4];
    {
        const uint32_t ao = (uint32_t)(((16*wid + (L & 15)) * AST + ((L >> 4) << 3)) * 2);
        #pragma unroll
        for (int kk = 0; kk < 4; kk++) {
            ldsm_x4(qh[kk], sQh_b + ao + (uint32_t)(kk * 32));
            ldsm_x4(ql[kk], sQl_b + ao + (uint32_t)(kk * 32));
        }
    }

    // B-frag smem offsets
    uint32_t bKo[4], bVo[4];
    #pragma unroll
    for (int p = 0; p < 4; p++) {
        bKo[p] = (uint32_t)(((p*16 + (L & 7) + ((L >> 4) << 3)) * AST
                             + (((L >> 3) & 1) << 3)) * 2);
        bVo[p] = (uint32_t)((((L & 7) + (((L >> 3) & 1) << 3)) * AST
                             + p*16 + ((L >> 4) << 3)) * 2);
    }

    float o[8][4];
    #pragma unroll
    for (int nf = 0; nf < 8; nf++)
        #pragma unroll
        for (int r = 0; r < 4; r++) o[nf][r] = 0.f;
    float m_run[2] = {-1e30f, -1e30f};
    float l_run[2] = {0.f, 0.f};

    const int r0g = q0 + 16*wid + (L >> 2);       // global row of c0/c1
    const int cnl = (L & 3) << 1;                 // local col pair base

    const int ntiles = 2*qt + 2;
    for (int jt = 0; jt < ntiles; jt++) {
        const int k0 = jt * 64;
        __syncthreads();
        // ---- load K/V tiles (both splits) ----
        for (int idx = tid; idx < 512; idx += 256) {
            const int row = idx >> 3;
            const int c8  = (idx & 7) << 3;
            const size_t go = base + (size_t)(k0 + row) * D_DIM + c8;
            *(uint4*)(sKh + row*AST + c8) = *(const uint4*)(g_kh + go);
            *(uint4*)(sKl + row*AST + c8) = *(const uint4*)(g_kl + go);
            *(uint4*)(sVh + row*AST + c8) = *(const uint4*)(g_vh + go);
            *(uint4*)(sVl + row*AST + c8) = *(const uint4*)(g_vl + go);
        }
        __syncthreads();

        // ---- S = Q K^T (bf16x3) ----
        float s[8][4];
        #pragma unroll
        for (int nf = 0; nf < 8; nf++)
            #pragma unroll
            for (int r = 0; r < 4; r++) s[nf][r] = 0.f;

        #pragma unroll
        for (int kk = 0; kk < 4; kk++) {
            const uint32_t kb = (uint32_t)(kk * 32);
            #pragma unroll
            for (int p = 0; p < 4; p++) {
                uint32_t tbh[4], tbl[4];
                ldsm_x4(tbh, sKh_b + bKo[p] + kb);
                ldsm_x4(tbl, sKl_b + bKo[p] + kb);
                mma_bf16(s[2*p],   qh[kk], tbh[0], tbh[1]);
                mma_bf16(s[2*p],   qh[kk], tbl[0], tbl[1]);
                mma_bf16(s[2*p],   ql[kk], tbh[0], tbh[1]);
                mma_bf16(s[2*p+1], qh[kk], tbh[2], tbh[3]);
                mma_bf16(s[2*p+1], qh[kk], tbl[2], tbl[3]);
                mma_bf16(s[2*p+1], ql[kk], tbh[2], tbh[3]);
            }
        }

        // ---- causal mask (last two tiles only) ----
        if (jt >= 2*qt) {
            #pragma unroll
            for (int nf = 0; nf < 8; nf++) {
                const int cn = k0 + 8*nf + cnl;
                if (cn     > r0g)     s[nf][0] = -1e30f;
                if (cn + 1 > r0g)     s[nf][1] = -1e30f;
                if (cn     > r0g + 8) s[nf][2] = -1e30f;
                if (cn + 1 > r0g + 8) s[nf][3] = -1e30f;
            }
        }

        // ---- online softmax (rows r0, r1=r0+8) ----
        float m0 = -1e30f, m1 = -1e30f;
        #pragma unroll
        for (int nf = 0; nf < 8; nf++) {
            m0 = fmaxf(m0, fmaxf(s[nf][0], s[nf][1]));
            m1 = fmaxf(m1, fmaxf(s[nf][2], s[nf][3]));
        }
        m0 = fmaxf(m0, __shfl_xor_sync(0xffffffffu, m0, 1));
        m0 = fmaxf(m0, __shfl_xor_sync(0xffffffffu, m0, 2));
        m1 = fmaxf(m1, __shfl_xor_sync(0xffffffffu, m1, 1));
        m1 = fmaxf(m1, __shfl_xor_sync(0xffffffffu, m1, 2));

        const float mn0 = fmaxf(m_run[0], m0);
        const float mn1 = fmaxf(m_run[1], m1);
        const float al0 = exp_fast(m_run[0] - mn0);
        const float al1 = exp_fast(m_run[1] - mn1);
        m_run[0] = mn0; m_run[1] = mn1;

        float sum0 = 0.f, sum1 = 0.f;
        uint32_t paH[4][4], paL[4][4];
        #pragma unroll
        for (int nf = 0; nf < 8; nf++) {
            float p0 = exp_fast(s[nf][0] - mn0);
            float p1 = exp_fast(s[nf][1] - mn0);
            float p2 = exp_fast(s[nf][2] - mn1);
            float p3 = exp_fast(s[nf][3] - mn1);
            sum0 += p0 + p1;
            sum1 += p2 + p3;
            const int kk = nf >> 1;
            const int u  = (nf & 1) << 1;       // 0 or 2 within A-frag
            split2(p0, p1, paH[kk][u],   paL[kk][u]);
            split2(p2, p3, paH[kk][u+1], paL[kk][u+1]);
        }
        sum0 += __shfl_xor_sync(0xffffffffu, sum0, 1);
        sum0 += __shfl_xor_sync(0xffffffffu, sum0, 2);
        sum1 += __shfl_xor_sync(0xffffffffu, sum1, 1);
        sum1 += __shfl_xor_sync(0xffffffffu, sum1, 2);
        l_run[0] = l_run[0] * al0 + sum0;
        l_run[1] = l_run[1] * al1 + sum1;

        #pragma unroll
        for (int nf = 0; nf < 8; nf++) {
            o[nf][0] *= al0; o[nf][1] *= al0;
            o[nf][2] *= al1; o[nf][3] *= al1;
        }

        // ---- O += P V (bf16x3), V via ldmatrix.trans ----
        #pragma unroll
        for (int kk = 0; kk < 4; kk++) {
            const uint32_t kr = (uint32_t)(kk * 16 * AST * 2);
            #pragma unroll
            for (int p = 0; p < 4; p++) {
                uint32_t tvh[4], tvl[4];
                ldsm_x4_t(tvh, sVh_b + bVo[p] + kr);
                ldsm_x4_t(tvl, sVl_b + bVo[p] + kr);
                mma_bf16(o[2*p],   paH[kk], tvh[0], tvh[1]);
                mma_bf16(o[2*p],   paH[kk], tvl[0], tvl[1]);
                mma_bf16(o[2*p],   paL[kk], tvh[0], tvh[1]);
                mma_bf16(o[2*p+1], paH[kk], tvh[2], tvh[3]);
                mma_bf16(o[2*p+1], paH[kk], tvl[2], tvl[3]);
                mma_bf16(o[2*p+1], paL[kk], tvh[2], tvh[3]);
            }
        }
    }

    // ---- epilogue: normalize, split to bf16 hi/lo, store ----
    const float inv0 = 1.f / l_run[0];
    const float inv1 = 1.f / l_run[1];
    #pragma unroll
    for (int nf = 0; nf < 8; nf++) {
        const int col = 8*nf + cnl;
        const size_t off0 = base + (size_t)r0g * D_DIM + col;
        const size_t off1 = off0 + (size_t)8 * D_DIM;
        uint32_t h, l;
        split2(o[nf][0] * inv0, o[nf][1] * inv0, h, l);
        *(uint32_t*)(g_oh + off0) = h;
        *(uint32_t*)(g_ol + off0) = l;
        split2(o[nf][2] * inv1, o[nf][3] * inv1, h, l);
        *(uint32_t*)(g_oh + off1) = h;
        *(uint32_t*)(g_ol + off1) = l;
    }
}

// ---------------------------------------------------------------------------
extern "C" void kernel_launch(void* const* d_in, const int* in_sizes, int n_in,
                              void* d_out, int out_size)
{
    (void)in_sizes; (void)n_in; (void)out_size;
    const float* x  = (const float*)d_in[0];
    const float* Wq = (const float*)d_in[2];
    const float* bq = (const float*)d_in[3];
    const float* Wk = (const float*)d_in[4];
    const float* bk = (const float*)d_in[5];
    const float* Wv = (const float*)d_in[6];
    const float* bv = (const float*)d_in[7];
    const float* Wo = (const float*)d_in[8];
    const float* bo = (const float*)d_in[9];
    float* out = (float*)d_out;

    __nv_bfloat16 *xh, *xl, *wh, *wl, *qh, *ql, *kh, *kl, *vh, *vl, *oh, *ol;
    cudaGetSymbolAddress((void**)&xh, g_xh);
    cudaGetSymbolAddress((void**)&xl, g_xl);
    cudaGetSymbolAddress((void**)&wh, g_wh);
    cudaGetSymbolAddress((void**)&wl, g_wl);
    cudaGetSymbolAddress((void**)&qh, g_qh);
    cudaGetSymbolAddress((void**)&ql, g_ql);
    cudaGetSymbolAddress((void**)&kh, g_kh);
    cudaGetSymbolAddress((void**)&kl, g_kl);
    cudaGetSymbolAddress((void**)&vh, g_vh);
    cudaGetSymbolAddress((void**)&vl, g_vl);
    cudaGetSymbolAddress((void**)&oh, g_oh);
    cudaGetSymbolAddress((void**)&ol, g_ol);

    cudaFuncSetAttribute(attn_mma,
                         cudaFuncAttributeMaxDynamicSharedMemorySize, ATTN_SMEM);

    const int WSZ = D_DIM * D_DIM;
    const int XN4 = (NROWS * D_DIM) / 4;
    const int WN4 = WSZ / 4;

    dim3 blk(256);

    // splits (x + 4 weights)
    split_kernel<<<(XN4 + 255) / 256, blk>>>(x,  xh, xl, XN4);
    split_kernel<<<(WN4 + 255) / 256, blk>>>(Wq, wh + 0*WSZ, wl + 0*WSZ, WN4);
    split_kernel<<<(WN4 + 255) / 256, blk>>>(Wk, wh + 1*WSZ, wl + 1*WSZ, WN4);
    split_kernel<<<(WN4 + 255) / 256, blk>>>(Wv, wh + 2*WSZ, wl + 2*WSZ, WN4);
    split_kernel<<<(WN4 + 255) / 256, blk>>>(Wo, wh + 3*WSZ, wl + 3*WSZ, WN4);

    // projections -> bf16 split outputs (Q prescaled by 1/sqrt(DK))
    dim3 gG(D_DIM / 128, NROWS / 128);      // (8, 64)
    gemm_bf16x3<1><<<gG, blk>>>(xh, xl, wh + 0*WSZ, wl + 0*WSZ, bq, 0.125f,
                                nullptr, qh, ql, D_DIM);
    gemm_bf16x3<1><<<gG, blk>>>(xh, xl, wh + 1*WSZ, wl + 1*WSZ, bk, 1.0f,
                                nullptr, kh, kl, D_DIM);
    gemm_bf16x3<1><<<gG, blk>>>(xh, xl, wh + 2*WSZ, wl + 2*WSZ, bv, 1.0f,
                                nullptr, vh, vl, D_DIM);

    // tensor-core flash attention
    dim3 gA(S_LEN / 128, B_SZ * NH);        // (16, 64)
    attn_mma<<<gA, blk, ATTN_SMEM>>>();

    // output projection (fp32 out)
    gemm_bf16x3<0><<<gG, blk>>>(oh, ol, wh + 3*WSZ, wl + 3*WSZ, bo, 1.0f,
                                out, nullptr, nullptr, D_DIM);
}

// round 8
// speedup vs baseline: 3.5428x; 1.1866x over previous
#include <cuda_runtime.h>
#include <cuda_bf16.h>
#include <cstdint>

// ---------------------------------------------------------------------------
// MultiHeadAttention, B=4 S=2048 D=1024 H=16 DK=64, fp32.
// R7: R6 pipeline + cp.async double-buffering in GEMM and attention.
//   - projections: HMMA bf16x3, 2-stage cp.async pipeline
//   - attention:   HMMA flash attention, K/V tiles double-buffered via cp.async
// ---------------------------------------------------------------------------

#define B_SZ   4
#define S_LEN  2048
#define D_DIM  1024
#define NH     16
#define DKH    64
#define NROWS  (B_SZ * S_LEN)          // 8192

// bf16 split scratch
__device__ __nv_bfloat16 g_xh[NROWS * D_DIM];
__device__ __nv_bfloat16 g_xl[NROWS * D_DIM];
__device__ __nv_bfloat16 g_wh[4][D_DIM * D_DIM];   // q,k,v,o
__device__ __nv_bfloat16 g_wl[4][D_DIM * D_DIM];
__device__ __nv_bfloat16 g_qh[NROWS * D_DIM];
__device__ __nv_bfloat16 g_ql[NROWS * D_DIM];
__device__ __nv_bfloat16 g_kh[NROWS * D_DIM];
__device__ __nv_bfloat16 g_kl[NROWS * D_DIM];
__device__ __nv_bfloat16 g_vh[NROWS * D_DIM];
__device__ __nv_bfloat16 g_vl[NROWS * D_DIM];
__device__ __nv_bfloat16 g_oh[NROWS * D_DIM];
__device__ __nv_bfloat16 g_ol[NROWS * D_DIM];

// ---------------------------------------------------------------------------
// helpers
// ---------------------------------------------------------------------------
__device__ __forceinline__ uint32_t smem_u32(const void* p) {
    uint32_t a;
    asm("{ .reg .u64 t; cvta.to.shared.u64 t, %1; cvt.u32.u64 %0, t; }"
        : "=r"(a) : "l"(p));
    return a;
}
__device__ __forceinline__ void cp16(uint32_t dst, const void* src) {
    asm volatile("cp.async.cg.shared.global [%0], [%1], 16;"
                 :: "r"(dst), "l"(src) : "memory");
}
#define CP_COMMIT()  asm volatile("cp.async.commit_group;" ::: "memory")
#define CP_WAIT0()   asm volatile("cp.async.wait_group 0;" ::: "memory")
#define CP_WAIT1()   asm volatile("cp.async.wait_group 1;" ::: "memory")

__device__ __forceinline__ void ldsm_x4(uint32_t* r, uint32_t addr) {
    asm volatile("ldmatrix.sync.aligned.m8n8.x4.shared.b16 {%0,%1,%2,%3}, [%4];"
                 : "=r"(r[0]), "=r"(r[1]), "=r"(r[2]), "=r"(r[3]) : "r"(addr));
}
__device__ __forceinline__ void ldsm_x4_t(uint32_t* r, uint32_t addr) {
    asm volatile("ldmatrix.sync.aligned.m8n8.x4.trans.shared.b16 {%0,%1,%2,%3}, [%4];"
                 : "=r"(r[0]), "=r"(r[1]), "=r"(r[2]), "=r"(r[3]) : "r"(addr));
}
__device__ __forceinline__ void mma_bf16(float* c, const uint32_t* a,
                                         uint32_t b0, uint32_t b1) {
    asm volatile("mma.sync.aligned.m16n8k16.row.col.f32.bf16.bf16.f32 "
                 "{%0,%1,%2,%3}, {%4,%5,%6,%7}, {%8,%9}, {%0,%1,%2,%3};"
                 : "+f"(c[0]), "+f"(c[1]), "+f"(c[2]), "+f"(c[3])
                 : "r"(a[0]), "r"(a[1]), "r"(a[2]), "r"(a[3]), "r"(b0), "r"(b1));
}
__device__ __forceinline__ uint32_t packbf(float lo, float hi) {
    uint32_t r;
    asm("cvt.rn.bf16x2.f32 %0, %1, %2;" : "=r"(r) : "f"(hi), "f"(lo));
    return r;
}
__device__ __forceinline__ void split2(float lo, float hi, uint32_t& h, uint32_t& l) {
    h = packbf(lo, hi);
    float hlo = __uint_as_float(h << 16);
    float hhi = __uint_as_float(h & 0xFFFF0000u);
    l = packbf(lo - hlo, hi - hhi);
}
__device__ __forceinline__ float exp_fast(float x) {
    float y = x * 1.4426950408889634f;
    y = fmaxf(y, -126.0f);
    float t = y + 12582912.0f;
    float n = t - 12582912.0f;
    float r = y - n;
    float p = 1.3333558146e-3f;
    p = fmaf(p, r, 9.6181291076e-3f);
    p = fmaf(p, r, 5.5504108664e-2f);
    p = fmaf(p, r, 2.4022650696e-1f);
    p = fmaf(p, r, 6.9314718056e-1f);
    p = fmaf(p, r, 1.0f);
    int e = (__float_as_int(t) - 0x4B400000 + 127) << 23;
    return p * __int_as_float(e);
}

// ---------------------------------------------------------------------------
// split: fp32 -> bf16 hi + bf16 residual
// ---------------------------------------------------------------------------
__global__ void __launch_bounds__(256)
split_kernel(const float* __restrict__ in, __nv_bfloat16* __restrict__ hi,
             __nv_bfloat16* __restrict__ lo, int n4)
{
    int i = blockIdx.x * blockDim.x + threadIdx.x;
    if (i >= n4) return;
    float4 v = ((const float4*)in)[i];
    uint32_t h0, l0, h1, l1;
    split2(v.x, v.y, h0, l0);
    split2(v.z, v.w, h1, l1);
    uint2 hh = {h0, h1}, ll = {l0, l1};
    ((uint2*)hi)[i] = hh;
    ((uint2*)lo)[i] = ll;
}

// ---------------------------------------------------------------------------
// HMMA GEMM with 2-stage cp.async pipeline:  C = (A@W^T + bias) * scale
// OUT_MODE 0: fp32 C.  OUT_MODE 1: bf16 split (Ch hi, Cl residual).
// CTA 128x128, warps 2(m)x4(n), warp tile 64x32, BK=32, double-buffered smem.
// ---------------------------------------------------------------------------
#define BK     32
#define SSTR   40
#define GK     1024
#define NCH    (GK / BK)               // 32 chunks? no: 1024/32 = 32
#define GTILE  (128 * SSTR)            // elements per tile
#define GEMM_SMEM (8 * GTILE * 2)      // 81920 B

template<int OUT_MODE>
__global__ void __launch_bounds__(256)
gemm_bf16x3(const __nv_bfloat16* __restrict__ Ah, const __nv_bfloat16* __restrict__ Al,
            const __nv_bfloat16* __restrict__ Wh, const __nv_bfloat16* __restrict__ Wl,
            const float* __restrict__ bias, float scale,
            float* __restrict__ Cf, __nv_bfloat16* __restrict__ Ch,
            __nv_bfloat16* __restrict__ Cl, int N)
{
    extern __shared__ __nv_bfloat16 gsm[];
    const uint32_t sb = smem_u32(gsm);

    const int tid = threadIdx.x;
    const int wid = tid >> 5;
    const int L   = tid & 31;
    const int wm  = wid >> 2;
    const int wn  = wid & 3;
    const int bn  = blockIdx.x * 128;
    const int bm  = blockIdx.y * 128;

    uint32_t aoff[4];
    #pragma unroll
    for (int mf = 0; mf < 4; mf++)
        aoff[mf] = (uint32_t)(((wm*64 + mf*16 + (L & 15)) * SSTR + ((L >> 4) << 3)) * 2);
    uint32_t boff[2];
    #pragma unroll
    for (int p = 0; p < 2; p++)
        boff[p] = (uint32_t)(((wn*32 + p*16 + (L & 7) + ((L >> 4) << 3)) * SSTR
                              + (((L >> 3) & 1) << 3)) * 2);

    float acc[4][4][4];
    #pragma unroll
    for (int mf = 0; mf < 4; mf++)
        #pragma unroll
        for (int nf = 0; nf < 4; nf++)
            #pragma unroll
            for (int r = 0; r < 4; r++) acc[mf][nf][r] = 0.f;

    const int lrow  = tid >> 1;
    const int lcolA = (tid & 1) * 16;
    const __nv_bfloat16* gsrc[4] = {
        Ah + (size_t)bm * GK, Al + (size_t)bm * GK,
        Wh + (size_t)bn * GK, Wl + (size_t)bn * GK };

    auto prefetch = [&](int ch, int b) {
        const int kbase = ch * BK;
        #pragma unroll
        for (int t = 0; t < 4; t++) {
            #pragma unroll
            for (int j = 0; j < 2; j++) {
                const int col = lcolA + j*8;
                const uint32_t sdst = sb +
                    (uint32_t)((((b*4 + t) * GTILE) + lrow*SSTR + col) * 2);
                cp16(sdst, gsrc[t] + (size_t)lrow * GK + kbase + col);
            }
        }
        CP_COMMIT();
    };

    prefetch(0, 0);
    for (int ch = 0; ch < NCH; ch++) {
        const int b = ch & 1;
        if (ch + 1 < NCH) { prefetch(ch + 1, b ^ 1); CP_WAIT1(); }
        else              { CP_WAIT0(); }
        __syncthreads();

        const uint32_t t0 = sb + (uint32_t)(b * 4 * GTILE * 2);
        const uint32_t tAh = t0;
        const uint32_t tAl = t0 + (uint32_t)(GTILE * 2);
        const uint32_t tWh = t0 + (uint32_t)(2 * GTILE * 2);
        const uint32_t tWl = t0 + (uint32_t)(3 * GTILE * 2);

        #pragma unroll
        for (int kk = 0; kk < BK; kk += 16) {
            const uint32_t kb = (uint32_t)(kk * 2);
            uint32_t af[4][4], bh[2][4], bl[2][4];
            #pragma unroll
            for (int mf = 0; mf < 4; mf++) ldsm_x4(af[mf], tAh + aoff[mf] + kb);
            #pragma unroll
            for (int p = 0; p < 2; p++) {
                ldsm_x4(bh[p], tWh + boff[p] + kb);
                ldsm_x4(bl[p], tWl + boff[p] + kb);
            }
            #pragma unroll
            for (int mf = 0; mf < 4; mf++)
                #pragma unroll
                for (int nf = 0; nf < 4; nf++) {
                    const int p = nf >> 1, h = (nf & 1) << 1;
                    mma_bf16(acc[mf][nf], af[mf], bh[p][h], bh[p][h+1]);
                    mma_bf16(acc[mf][nf], af[mf], bl[p][h], bl[p][h+1]);
                }
            #pragma unroll
            for (int mf = 0; mf < 4; mf++) ldsm_x4(af[mf], tAl + aoff[mf] + kb);
            #pragma unroll
            for (int mf = 0; mf < 4; mf++)
                #pragma unroll
                for (int nf = 0; nf < 4; nf++) {
                    const int p = nf >> 1, h = (nf & 1) << 1;
                    mma_bf16(acc[mf][nf], af[mf], bh[p][h], bh[p][h+1]);
                }
        }
        __syncthreads();
    }

    #pragma unroll
    for (int mf = 0; mf < 4; mf++) {
        const int row0 = bm + wm*64 + mf*16 + (L >> 2);
        #pragma unroll
        for (int nf = 0; nf < 4; nf++) {
            const int col = bn + wn*32 + nf*8 + ((L & 3) << 1);
            const float b0 = bias[col], b1 = bias[col + 1];
            float v00 = (acc[mf][nf][0] + b0) * scale;
            float v01 = (acc[mf][nf][1] + b1) * scale;
            float v10 = (acc[mf][nf][2] + b0) * scale;
            float v11 = (acc[mf][nf][3] + b1) * scale;
            if (OUT_MODE == 0) {
                float2 a0 = {v00, v01}, a1 = {v10, v11};
                *(float2*)(Cf + (size_t)row0 * N + col)       = a0;
                *(float2*)(Cf + (size_t)(row0 + 8) * N + col) = a1;
            } else {
                uint32_t h, l;
                split2(v00, v01, h, l);
                *(uint32_t*)(Ch + (size_t)row0 * N + col) = h;
                *(uint32_t*)(Cl + (size_t)row0 * N + col) = l;
                split2(v10, v11, h, l);
                *(uint32_t*)(Ch + (size_t)(row0 + 8) * N + col) = h;
                *(uint32_t*)(Cl + (size_t)(row0 + 8) * N + col) = l;
            }
        }
    }
}

// ---------------------------------------------------------------------------
// HMMA flash attention, causal, K/V double-buffered via cp.async.
// CTA = 128 queries x one (b,h), 8 warps; warp w owns rows 16w..16w+15.
// smem: Q (hi/lo) + 2 x [Kh,Kl,Vh,Vl] tiles of 64 rows, stride 72 bf16.
// ---------------------------------------------------------------------------
#define AST    72
#define KTILE  (64 * AST)                              // elements per KV array
#define ATTN_SMEM ((2*128*AST + 2*4*KTILE) * 2)        // 110592 B

__global__ void __launch_bounds__(256)
attn_mma()
{
    extern __shared__ __nv_bfloat16 smb[];
    __nv_bfloat16* sQh = smb;
    __nv_bfloat16* sQl = sQh + 128*AST;
    __nv_bfloat16* sKV = sQl + 128*AST;    // [2][4][KTILE]

    const int tid = threadIdx.x;
    const int wid = tid >> 5;
    const int L   = tid & 31;
    const int qt  = (int)gridDim.x - 1 - (int)blockIdx.x;
    const int bh  = blockIdx.y;
    const size_t base = (size_t)(bh >> 4) * S_LEN * D_DIM + (size_t)(bh & 15) * DKH;
    const int q0 = qt * 128;

    const uint32_t sQh_b = smem_u32(sQh);
    const uint32_t sQl_b = smem_u32(sQl);
    const uint32_t kvb   = smem_u32(sKV);

    auto prefetch_kv = [&](int jt, int b) {
        const int k0 = jt * 64;
        const __nv_bfloat16* gs[4] = {g_kh, g_kl, g_vh, g_vl};
        #pragma unroll
        for (int it = 0; it < 2; it++) {
            const int idx = tid + it * 256;
            const int row = idx >> 3, c8 = (idx & 7) << 3;
            const size_t go = base + (size_t)(k0 + row) * D_DIM + c8;
            #pragma unroll
            for (int t = 0; t < 4; t++) {
                const uint32_t sdst = kvb +
                    (uint32_t)((((b*4 + t) * KTILE) + row*AST + c8) * 2);
                cp16(sdst, gs[t] + go);
            }
        }
        CP_COMMIT();
    };

    // ---- load Q tile (both splits) + first KV prefetch ----
    prefetch_kv(0, 0);
    for (int idx = tid; idx < 1024; idx += 256) {
        const int row = idx >> 3;
        const int c8  = (idx & 7) << 3;
        const size_t go = base + (size_t)(q0 + row) * D_DIM + c8;
        *(uint4*)(sQh + row*AST + c8) = *(const uint4*)(g_qh + go);
        *(uint4*)(sQl + row*AST + c8) = *(const uint4*)(g_ql + go);
    }
    __syncthreads();

    // ---- Q fragments (held for whole kernel) ----
    uint32_t qh[4][4], ql[4][4];
    {
        const uint32_t ao = (uint32_t)(((16*wid + (L & 15)) * AST + ((L >> 4) << 3)) * 2);
        #pragma unroll
        for (int kk = 0; kk < 4; kk++) {
            ldsm_x4(qh[kk], sQh_b + ao + (uint32_t)(kk * 32));
            ldsm_x4(ql[kk], sQl_b + ao + (uint32_t)(kk * 32));
        }
    }

    uint32_t bKo[4], bVo[4];
    #pragma unroll
    for (int p = 0; p < 4; p++) {
        bKo[p] = (uint32_t)(((p*16 + (L & 7) + ((L >> 4) << 3)) * AST
                             + (((L >> 3) & 1) << 3)) * 2);
        bVo[p] = (uint32_t)((((L & 7) + (((L >> 3) & 1) << 3)) * AST
                             + p*16 + ((L >> 4) << 3)) * 2);
    }

    float o[8][4];
    #pragma unroll
    for (int nf = 0; nf < 8; nf++)
        #pragma unroll
        for (int r = 0; r < 4; r++) o[nf][r] = 0.f;
    float m_run[2] = {-1e30f, -1e30f};
    float l_run[2] = {0.f, 0.f};

    const int r0g = q0 + 16*wid + (L >> 2);
    const int cnl = (L & 3) << 1;

    const int ntiles = 2*qt + 2;
    for (int jt = 0; jt < ntiles; jt++) {
        const int k0 = jt * 64;
        const int b = jt & 1;
        if (jt + 1 < ntiles) { prefetch_kv(jt + 1, b ^ 1); CP_WAIT1(); }
        else                 { CP_WAIT0(); }
        __syncthreads();

        const uint32_t tKh = kvb + (uint32_t)((b*4 + 0) * KTILE * 2);
        const uint32_t tKl = kvb + (uint32_t)((b*4 + 1) * KTILE * 2);
        const uint32_t tVh = kvb + (uint32_t)((b*4 + 2) * KTILE * 2);
        const uint32_t tVl = kvb + (uint32_t)((b*4 + 3) * KTILE * 2);

        // ---- S = Q K^T (bf16x3) ----
        float s[8][4];
        #pragma unroll
        for (int nf = 0; nf < 8; nf++)
            #pragma unroll
            for (int r = 0; r < 4; r++) s[nf][r] = 0.f;

        #pragma unroll
        for (int kk = 0; kk < 4; kk++) {
            const uint32_t kb = (uint32_t)(kk * 32);
            #pragma unroll
            for (int p = 0; p < 4; p++) {
                uint32_t tbh[4], tbl[4];
                ldsm_x4(tbh, tKh + bKo[p] + kb);
                ldsm_x4(tbl, tKl + bKo[p] + kb);
                mma_bf16(s[2*p],   qh[kk], tbh[0], tbh[1]);
                mma_bf16(s[2*p],   qh[kk], tbl[0], tbl[1]);
                mma_bf16(s[2*p],   ql[kk], tbh[0], tbh[1]);
                mma_bf16(s[2*p+1], qh[kk], tbh[2], tbh[3]);
                mma_bf16(s[2*p+1], qh[kk], tbl[2], tbl[3]);
                mma_bf16(s[2*p+1], ql[kk], tbh[2], tbh[3]);
            }
        }

        // ---- causal mask (last two tiles only) ----
        if (jt >= 2*qt) {
            #pragma unroll
            for (int nf = 0; nf < 8; nf++) {
                const int cn = k0 + 8*nf + cnl;
                if (cn     > r0g)     s[nf][0] = -1e30f;
                if (cn + 1 > r0g)     s[nf][1] = -1e30f;
                if (cn     > r0g + 8) s[nf][2] = -1e30f;
                if (cn + 1 > r0g + 8) s[nf][3] = -1e30f;
            }
        }

        // ---- online softmax ----
        float m0 = -1e30f, m1 = -1e30f;
        #pragma unroll
        for (int nf = 0; nf < 8; nf++) {
            m0 = fmaxf(m0, fmaxf(s[nf][0], s[nf][1]));
            m1 = fmaxf(m1, fmaxf(s[nf][2], s[nf][3]));
        }
        m0 = fmaxf(m0, __shfl_xor_sync(0xffffffffu, m0, 1));
        m0 = fmaxf(m0, __shfl_xor_sync(0xffffffffu, m0, 2));
        m1 = fmaxf(m1, __shfl_xor_sync(0xffffffffu, m1, 1));
        m1 = fmaxf(m1, __shfl_xor_sync(0xffffffffu, m1, 2));

        const float mn0 = fmaxf(m_run[0], m0);
        const float mn1 = fmaxf(m_run[1], m1);
        const float al0 = exp_fast(m_run[0] - mn0);
        const float al1 = exp_fast(m_run[1] - mn1);
        m_run[0] = mn0; m_run[1] = mn1;

        float sum0 = 0.f, sum1 = 0.f;
        uint32_t paH[4][4], paL[4][4];
        #pragma unroll
        for (int nf = 0; nf < 8; nf++) {
            float p0 = exp_fast(s[nf][0] - mn0);
            float p1 = exp_fast(s[nf][1] - mn0);
            float p2 = exp_fast(s[nf][2] - mn1);
            float p3 = exp_fast(s[nf][3] - mn1);
            sum0 += p0 + p1;
            sum1 += p2 + p3;
            const int kk = nf >> 1;
            const int u  = (nf & 1) << 1;
            split2(p0, p1, paH[kk][u],   paL[kk][u]);
            split2(p2, p3, paH[kk][u+1], paL[kk][u+1]);
        }
        sum0 += __shfl_xor_sync(0xffffffffu, sum0, 1);
        sum0 += __shfl_xor_sync(0xffffffffu, sum0, 2);
        sum1 += __shfl_xor_sync(0xffffffffu, sum1, 1);
        sum1 += __shfl_xor_sync(0xffffffffu, sum1, 2);
        l_run[0] = l_run[0] * al0 + sum0;
        l_run[1] = l_run[1] * al1 + sum1;

        #pragma unroll
        for (int nf = 0; nf < 8; nf++) {
            o[nf][0] *= al0; o[nf][1] *= al0;
            o[nf][2] *= al1; o[nf][3] *= al1;
        }

        // ---- O += P V (bf16x3) ----
        #pragma unroll
        for (int kk = 0; kk < 4; kk++) {
            const uint32_t kr = (uint32_t)(kk * 16 * AST * 2);
            #pragma unroll
            for (int p = 0; p < 4; p++) {
                uint32_t tvh[4], tvl[4];
                ldsm_x4_t(tvh, tVh + bVo[p] + kr);
                ldsm_x4_t(tvl, tVl + bVo[p] + kr);
                mma_bf16(o[2*p],   paH[kk], tvh[0], tvh[1]);
                mma_bf16(o[2*p],   paH[kk], tvl[0], tvl[1]);
                mma_bf16(o[2*p],   paL[kk], tvh[0], tvh[1]);
                mma_bf16(o[2*p+1], paH[kk], tvh[2], tvh[3]);
                mma_bf16(o[2*p+1], paH[kk], tvl[2], tvl[3]);
                mma_bf16(o[2*p+1], paL[kk], tvh[2], tvh[3]);
            }
        }
        __syncthreads();   // all reads of buf b done before jt+2 prefetch
    }

    // ---- epilogue: normalize, split, store ----
    const float inv0 = 1.f / l_run[0];
    const float inv1 = 1.f / l_run[1];
    #pragma unroll
    for (int nf = 0; nf < 8; nf++) {
        const int col = 8*nf + cnl;
        const size_t off0 = base + (size_t)r0g * D_DIM + col;
        const size_t off1 = off0 + (size_t)8 * D_DIM;
        uint32_t h, l;
        split2(o[nf][0] * inv0, o[nf][1] * inv0, h, l);
        *(uint32_t*)(g_oh + off0) = h;
        *(uint32_t*)(g_ol + off0) = l;
        split2(o[nf][2] * inv1, o[nf][3] * inv1, h, l);
        *(uint32_t*)(g_oh + off1) = h;
        *(uint32_t*)(g_ol + off1) = l;
    }
}

// ---------------------------------------------------------------------------
extern "C" void kernel_launch(void* const* d_in, const int* in_sizes, int n_in,
                              void* d_out, int out_size)
{
    (void)in_sizes; (void)n_in; (void)out_size;
    const float* x  = (const float*)d_in[0];
    const float* Wq = (const float*)d_in[2];
    const float* bq = (const float*)d_in[3];
    const float* Wk = (const float*)d_in[4];
    const float* bk = (const float*)d_in[5];
    const float* Wv = (const float*)d_in[6];
    const float* bv = (const float*)d_in[7];
    const float* Wo = (const float*)d_in[8];
    const float* bo = (const float*)d_in[9];
    float* out = (float*)d_out;

    __nv_bfloat16 *xh, *xl, *wh, *wl, *qh, *ql, *kh, *kl, *vh, *vl, *oh, *ol;
    cudaGetSymbolAddress((void**)&xh, g_xh);
    cudaGetSymbolAddress((void**)&xl, g_xl);
    cudaGetSymbolAddress((void**)&wh, g_wh);
    cudaGetSymbolAddress((void**)&wl, g_wl);
    cudaGetSymbolAddress((void**)&qh, g_qh);
    cudaGetSymbolAddress((void**)&ql, g_ql);
    cudaGetSymbolAddress((void**)&kh, g_kh);
    cudaGetSymbolAddress((void**)&kl, g_kl);
    cudaGetSymbolAddress((void**)&vh, g_vh);
    cudaGetSymbolAddress((void**)&vl, g_vl);
    cudaGetSymbolAddress((void**)&oh, g_oh);
    cudaGetSymbolAddress((void**)&ol, g_ol);

    cudaFuncSetAttribute(attn_mma,
                         cudaFuncAttributeMaxDynamicSharedMemorySize, ATTN_SMEM);
    cudaFuncSetAttribute(gemm_bf16x3<0>,
                         cudaFuncAttributeMaxDynamicSharedMemorySize, GEMM_SMEM);
    cudaFuncSetAttribute(gemm_bf16x3<1>,
                         cudaFuncAttributeMaxDynamicSharedMemorySize, GEMM_SMEM);

    const int WSZ = D_DIM * D_DIM;
    const int XN4 = (NROWS * D_DIM) / 4;
    const int WN4 = WSZ / 4;

    dim3 blk(256);

    split_kernel<<<(XN4 + 255) / 256, blk>>>(x,  xh, xl, XN4);
    split_kernel<<<(WN4 + 255) / 256, blk>>>(Wq, wh + 0*WSZ, wl + 0*WSZ, WN4);
    split_kernel<<<(WN4 + 255) / 256, blk>>>(Wk, wh + 1*WSZ, wl + 1*WSZ, WN4);
    split_kernel<<<(WN4 + 255) / 256, blk>>>(Wv, wh + 2*WSZ, wl + 2*WSZ, WN4);
    split_kernel<<<(WN4 + 255) / 256, blk>>>(Wo, wh + 3*WSZ, wl + 3*WSZ, WN4);

    dim3 gG(D_DIM / 128, NROWS / 128);      // (8, 64)
    gemm_bf16x3<1><<<gG, blk, GEMM_SMEM>>>(xh, xl, wh + 0*WSZ, wl + 0*WSZ, bq,
                                           0.125f, nullptr, qh, ql, D_DIM);
    gemm_bf16x3<1><<<gG, blk, GEMM_SMEM>>>(xh, xl, wh + 1*WSZ, wl + 1*WSZ, bk,
                                           1.0f, nullptr, kh, kl, D_DIM);
    gemm_bf16x3<1><<<gG, blk, GEMM_SMEM>>>(xh, xl, wh + 2*WSZ, wl + 2*WSZ, bv,
                                           1.0f, nullptr, vh, vl, D_DIM);

    dim3 gA(S_LEN / 128, B_SZ * NH);        // (16, 64)
    attn_mma<<<gA, blk, ATTN_SMEM>>>();

    gemm_bf16x3<0><<<gG, blk, GEMM_SMEM>>>(oh, ol, wh + 3*WSZ, wl + 3*WSZ, bo,
                                           1.0f, out, nullptr, nullptr, D_DIM);
}

// round 9
// speedup vs baseline: 3.7079x; 1.0466x over previous
#include <cuda_runtime.h>
#include <cuda_bf16.h>
#include <cstdint>

// ---------------------------------------------------------------------------
// MultiHeadAttention, B=4 S=2048 D=1024 H=16 DK=64, fp32.
// R8: attention software-pipelined: S-MMA(jt+1) issued before softmax(jt)
//     (tensor/FFMA overlap), KV triple-buffered cp.async ring.
//     Projections: R7 HMMA bf16x3 with 2-stage cp.async pipeline (unchanged).
// ---------------------------------------------------------------------------

#define B_SZ   4
#define S_LEN  2048
#define D_DIM  1024
#define NH     16
#define DKH    64
#define NROWS  (B_SZ * S_LEN)          // 8192

__device__ __nv_bfloat16 g_xh[NROWS * D_DIM];
__device__ __nv_bfloat16 g_xl[NROWS * D_DIM];
__device__ __nv_bfloat16 g_wh[4][D_DIM * D_DIM];   // q,k,v,o
__device__ __nv_bfloat16 g_wl[4][D_DIM * D_DIM];
__device__ __nv_bfloat16 g_qh[NROWS * D_DIM];
__device__ __nv_bfloat16 g_ql[NROWS * D_DIM];
__device__ __nv_bfloat16 g_kh[NROWS * D_DIM];
__device__ __nv_bfloat16 g_kl[NROWS * D_DIM];
__device__ __nv_bfloat16 g_vh[NROWS * D_DIM];
__device__ __nv_bfloat16 g_vl[NROWS * D_DIM];
__device__ __nv_bfloat16 g_oh[NROWS * D_DIM];
__device__ __nv_bfloat16 g_ol[NROWS * D_DIM];

// ---------------------------------------------------------------------------
// helpers
// ---------------------------------------------------------------------------
__device__ __forceinline__ uint32_t smem_u32(const void* p) {
    uint32_t a;
    asm("{ .reg .u64 t; cvta.to.shared.u64 t, %1; cvt.u32.u64 %0, t; }"
        : "=r"(a) : "l"(p));
    return a;
}
__device__ __forceinline__ void cp16(uint32_t dst, const void* src) {
    asm volatile("cp.async.cg.shared.global [%0], [%1], 16;"
                 :: "r"(dst), "l"(src) : "memory");
}
#define CP_COMMIT()  asm volatile("cp.async.commit_group;" ::: "memory")
#define CP_WAIT0()   asm volatile("cp.async.wait_group 0;" ::: "memory")
#define CP_WAIT1()   asm volatile("cp.async.wait_group 1;" ::: "memory")

__device__ __forceinline__ void ldsm_x4(uint32_t* r, uint32_t addr) {
    asm volatile("ldmatrix.sync.aligned.m8n8.x4.shared.b16 {%0,%1,%2,%3}, [%4];"
                 : "=r"(r[0]), "=r"(r[1]), "=r"(r[2]), "=r"(r[3]) : "r"(addr));
}
__device__ __forceinline__ void ldsm_x4_t(uint32_t* r, uint32_t addr) {
    asm volatile("ldmatrix.sync.aligned.m8n8.x4.trans.shared.b16 {%0,%1,%2,%3}, [%4];"
                 : "=r"(r[0]), "=r"(r[1]), "=r"(r[2]), "=r"(r[3]) : "r"(addr));
}
__device__ __forceinline__ void mma_bf16(float* c, const uint32_t* a,
                                         uint32_t b0, uint32_t b1) {
    asm volatile("mma.sync.aligned.m16n8k16.row.col.f32.bf16.bf16.f32 "
                 "{%0,%1,%2,%3}, {%4,%5,%6,%7}, {%8,%9}, {%0,%1,%2,%3};"
                 : "+f"(c[0]), "+f"(c[1]), "+f"(c[2]), "+f"(c[3])
                 : "r"(a[0]), "r"(a[1]), "r"(a[2]), "r"(a[3]), "r"(b0), "r"(b1));
}
__device__ __forceinline__ uint32_t packbf(float lo, float hi) {
    uint32_t r;
    asm("cvt.rn.bf16x2.f32 %0, %1, %2;" : "=r"(r) : "f"(hi), "f"(lo));
    return r;
}
__device__ __forceinline__ void split2(float lo, float hi, uint32_t& h, uint32_t& l) {
    h = packbf(lo, hi);
    float hlo = __uint_as_float(h << 16);
    float hhi = __uint_as_float(h & 0xFFFF0000u);
    l = packbf(lo - hlo, hi - hhi);
}
__device__ __forceinline__ float exp_fast(float x) {
    float y = x * 1.4426950408889634f;
    y = fmaxf(y, -126.0f);
    float t = y + 12582912.0f;
    float n = t - 12582912.0f;
    float r = y - n;
    float p = 1.3333558146e-3f;
    p = fmaf(p, r, 9.6181291076e-3f);
    p = fmaf(p, r, 5.5504108664e-2f);
    p = fmaf(p, r, 2.4022650696e-1f);
    p = fmaf(p, r, 6.9314718056e-1f);
    p = fmaf(p, r, 1.0f);
    int e = (__float_as_int(t) - 0x4B400000 + 127) << 23;
    return p * __int_as_float(e);
}

// ---------------------------------------------------------------------------
// split: fp32 -> bf16 hi + bf16 residual
// ---------------------------------------------------------------------------
__global__ void __launch_bounds__(256)
split_kernel(const float* __restrict__ in, __nv_bfloat16* __restrict__ hi,
             __nv_bfloat16* __restrict__ lo, int n4)
{
    int i = blockIdx.x * blockDim.x + threadIdx.x;
    if (i >= n4) return;
    float4 v = ((const float4*)in)[i];
    uint32_t h0, l0, h1, l1;
    split2(v.x, v.y, h0, l0);
    split2(v.z, v.w, h1, l1);
    uint2 hh = {h0, h1}, ll = {l0, l1};
    ((uint2*)hi)[i] = hh;
    ((uint2*)lo)[i] = ll;
}

// ---------------------------------------------------------------------------
// HMMA GEMM with 2-stage cp.async pipeline:  C = (A@W^T + bias) * scale
// (unchanged from R7)
// ---------------------------------------------------------------------------
#define BK     32
#define SSTR   40
#define GK     1024
#define NCH    (GK / BK)
#define GTILE  (128 * SSTR)
#define GEMM_SMEM (8 * GTILE * 2)      // 81920 B

template<int OUT_MODE>
__global__ void __launch_bounds__(256)
gemm_bf16x3(const __nv_bfloat16* __restrict__ Ah, const __nv_bfloat16* __restrict__ Al,
            const __nv_bfloat16* __restrict__ Wh, const __nv_bfloat16* __restrict__ Wl,
            const float* __restrict__ bias, float scale,
            float* __restrict__ Cf, __nv_bfloat16* __restrict__ Ch,
            __nv_bfloat16* __restrict__ Cl, int N)
{
    extern __shared__ __nv_bfloat16 gsm[];
    const uint32_t sb = smem_u32(gsm);

    const int tid = threadIdx.x;
    const int wid = tid >> 5;
    const int L   = tid & 31;
    const int wm  = wid >> 2;
    const int wn  = wid & 3;
    const int bn  = blockIdx.x * 128;
    const int bm  = blockIdx.y * 128;

    uint32_t aoff[4];
    #pragma unroll
    for (int mf = 0; mf < 4; mf++)
        aoff[mf] = (uint32_t)(((wm*64 + mf*16 + (L & 15)) * SSTR + ((L >> 4) << 3)) * 2);
    uint32_t boff[2];
    #pragma unroll
    for (int p = 0; p < 2; p++)
        boff[p] = (uint32_t)(((wn*32 + p*16 + (L & 7) + ((L >> 4) << 3)) * SSTR
                              + (((L >> 3) & 1) << 3)) * 2);

    float acc[4][4][4];
    #pragma unroll
    for (int mf = 0; mf < 4; mf++)
        #pragma unroll
        for (int nf = 0; nf < 4; nf++)
            #pragma unroll
            for (int r = 0; r < 4; r++) acc[mf][nf][r] = 0.f;

    const int lrow  = tid >> 1;
    const int lcolA = (tid & 1) * 16;
    const __nv_bfloat16* gsrc[4] = {
        Ah + (size_t)bm * GK, Al + (size_t)bm * GK,
        Wh + (size_t)bn * GK, Wl + (size_t)bn * GK };

    auto prefetch = [&](int ch, int b) {
        const int kbase = ch * BK;
        #pragma unroll
        for (int t = 0; t < 4; t++) {
            #pragma unroll
            for (int j = 0; j < 2; j++) {
                const int col = lcolA + j*8;
                const uint32_t sdst = sb +
                    (uint32_t)((((b*4 + t) * GTILE) + lrow*SSTR + col) * 2);
                cp16(sdst, gsrc[t] + (size_t)lrow * GK + kbase + col);
            }
        }
        CP_COMMIT();
    };

    prefetch(0, 0);
    for (int ch = 0; ch < NCH; ch++) {
        const int b = ch & 1;
        if (ch + 1 < NCH) { prefetch(ch + 1, b ^ 1); CP_WAIT1(); }
        else              { CP_WAIT0(); }
        __syncthreads();

        const uint32_t t0 = sb + (uint32_t)(b * 4 * GTILE * 2);
        const uint32_t tAh = t0;
        const uint32_t tAl = t0 + (uint32_t)(GTILE * 2);
        const uint32_t tWh = t0 + (uint32_t)(2 * GTILE * 2);
        const uint32_t tWl = t0 + (uint32_t)(3 * GTILE * 2);

        #pragma unroll
        for (int kk = 0; kk < BK; kk += 16) {
            const uint32_t kb = (uint32_t)(kk * 2);
            uint32_t af[4][4], bh[2][4], bl[2][4];
            #pragma unroll
            for (int mf = 0; mf < 4; mf++) ldsm_x4(af[mf], tAh + aoff[mf] + kb);
            #pragma unroll
            for (int p = 0; p < 2; p++) {
                ldsm_x4(bh[p], tWh + boff[p] + kb);
                ldsm_x4(bl[p], tWl + boff[p] + kb);
            }
            #pragma unroll
            for (int mf = 0; mf < 4; mf++)
                #pragma unroll
                for (int nf = 0; nf < 4; nf++) {
                    const int p = nf >> 1, h = (nf & 1) << 1;
                    mma_bf16(acc[mf][nf], af[mf], bh[p][h], bh[p][h+1]);
                    mma_bf16(acc[mf][nf], af[mf], bl[p][h], bl[p][h+1]);
                }
            #pragma unroll
            for (int mf = 0; mf < 4; mf++) ldsm_x4(af[mf], tAl + aoff[mf] + kb);
            #pragma unroll
            for (int mf = 0; mf < 4; mf++)
                #pragma unroll
                for (int nf = 0; nf < 4; nf++) {
                    const int p = nf >> 1, h = (nf & 1) << 1;
                    mma_bf16(acc[mf][nf], af[mf], bh[p][h], bh[p][h+1]);
                }
        }
        __syncthreads();
    }

    #pragma unroll
    for (int mf = 0; mf < 4; mf++) {
        const int row0 = bm + wm*64 + mf*16 + (L >> 2);
        #pragma unroll
        for (int nf = 0; nf < 4; nf++) {
            const int col = bn + wn*32 + nf*8 + ((L & 3) << 1);
            const float b0 = bias[col], b1 = bias[col + 1];
            float v00 = (acc[mf][nf][0] + b0) * scale;
            float v01 = (acc[mf][nf][1] + b1) * scale;
            float v10 = (acc[mf][nf][2] + b0) * scale;
            float v11 = (acc[mf][nf][3] + b1) * scale;
            if (OUT_MODE == 0) {
                float2 a0 = {v00, v01}, a1 = {v10, v11};
                *(float2*)(Cf + (size_t)row0 * N + col)       = a0;
                *(float2*)(Cf + (size_t)(row0 + 8) * N + col) = a1;
            } else {
                uint32_t h, l;
                split2(v00, v01, h, l);
                *(uint32_t*)(Ch + (size_t)row0 * N + col) = h;
                *(uint32_t*)(Cl + (size_t)row0 * N + col) = l;
                split2(v10, v11, h, l);
                *(uint32_t*)(Ch + (size_t)(row0 + 8) * N + col) = h;
                *(uint32_t*)(Cl + (size_t)(row0 + 8) * N + col) = l;
            }
        }
    }
}

// ---------------------------------------------------------------------------
// HMMA flash attention, causal, software-pipelined.
// Per iteration jt:  wait+sync -> S-MMA(jt+1) -> prefetch KV(jt+2)
//                    -> softmax(jt) (overlaps in-flight HMMAs) -> PV(jt).
// KV tiles in a 3-deep cp.async ring; s_cur/s_next ping-pong via 2x unroll.
// ---------------------------------------------------------------------------
#define AST    72
#define KTILE  (64 * AST)
#define ATTN_SMEM ((2*128*AST + 3*4*KTILE) * 2)    // 147456 B

__global__ void __launch_bounds__(256)
attn_mma()
{
    extern __shared__ __nv_bfloat16 smb[];
    __nv_bfloat16* sQh = smb;
    __nv_bfloat16* sQl = sQh + 128*AST;
    __nv_bfloat16* sKV = sQl + 128*AST;    // [3][4][KTILE]

    const int tid = threadIdx.x;
    const int wid = tid >> 5;
    const int L   = tid & 31;
    const int qt  = (int)gridDim.x - 1 - (int)blockIdx.x;
    const int bh  = blockIdx.y;
    const size_t base = (size_t)(bh >> 4) * S_LEN * D_DIM + (size_t)(bh & 15) * DKH;
    const int q0 = qt * 128;

    const uint32_t sQh_b = smem_u32(sQh);
    const uint32_t sQl_b = smem_u32(sQl);
    const uint32_t kvb   = smem_u32(sKV);

    auto prefetch_kv = [&](int jt, int b) {
        const int k0 = jt * 64;
        const __nv_bfloat16* gs[4] = {g_kh, g_kl, g_vh, g_vl};
        #pragma unroll
        for (int it = 0; it < 2; it++) {
            const int idx = tid + it * 256;
            const int row = idx >> 3, c8 = (idx & 7) << 3;
            const size_t go = base + (size_t)(k0 + row) * D_DIM + c8;
            #pragma unroll
            for (int t = 0; t < 4; t++) {
                const uint32_t sdst = kvb +
                    (uint32_t)((((b*4 + t) * KTILE) + row*AST + c8) * 2);
                cp16(sdst, gs[t] + go);
            }
        }
        CP_COMMIT();
    };

    const int ntiles = 2*qt + 2;           // always even, >= 2

    // ---- prologue: prefetch tiles 0,1 + load Q ----
    prefetch_kv(0, 0);
    prefetch_kv(1, 1);
    for (int idx = tid; idx < 1024; idx += 256) {
        const int row = idx >> 3;
        const int c8  = (idx & 7) << 3;
        const size_t go = base + (size_t)(q0 + row) * D_DIM + c8;
        *(uint4*)(sQh + row*AST + c8) = *(const uint4*)(g_qh + go);
        *(uint4*)(sQl + row*AST + c8) = *(const uint4*)(g_ql + go);
    }
    CP_WAIT1();                            // tile 0 resident
    __syncthreads();

    // ---- Q fragments (held for whole kernel) ----
    uint32_t qh[4][4], ql[4][4];
    {
        const uint32_t ao = (uint32_t)(((16*wid + (L & 15)) * AST + ((L >> 4) << 3)) * 2);
        #pragma unroll
        for (int kk = 0; kk < 4; kk++) {
            ldsm_x4(qh[kk], sQh_b + ao + (uint32_t)(kk * 32));
            ldsm_x4(ql[kk], sQl_b + ao + (uint32_t)(kk * 32));
        }
    }

    uint32_t bKo[4], bVo[4];
    #pragma unroll
    for (int p = 0; p < 4; p++) {
        bKo[p] = (uint32_t)(((p*16 + (L & 7) + ((L >> 4) << 3)) * AST
                             + (((L >> 3) & 1) << 3)) * 2);
        bVo[p] = (uint32_t)((((L & 7) + (((L >> 3) & 1) << 3)) * AST
                             + p*16 + ((L >> 4) << 3)) * 2);
    }

    float o[8][4];
    #pragma unroll
    for (int nf = 0; nf < 8; nf++)
        #pragma unroll
        for (int r = 0; r < 4; r++) o[nf][r] = 0.f;
    float m_run[2] = {-1e30f, -1e30f};
    float l_run[2] = {0.f, 0.f};

    const int r0g = q0 + 16*wid + (L >> 2);
    const int cnl = (L & 3) << 1;

    // ---- S-MMA of tile t (buffer b) into s; apply causal mask if needed ----
    auto smma = [&](int t, int b, float (&s)[8][4]) {
        const uint32_t tKh = kvb + (uint32_t)((b*4 + 0) * KTILE * 2);
        const uint32_t tKl = kvb + (uint32_t)((b*4 + 1) * KTILE * 2);
        #pragma unroll
        for (int nf = 0; nf < 8; nf++)
            #pragma unroll
            for (int r = 0; r < 4; r++) s[nf][r] = 0.f;
        #pragma unroll
        for (int kk = 0; kk < 4; kk++) {
            const uint32_t kb = (uint32_t)(kk * 32);
            #pragma unroll
            for (int p = 0; p < 4; p++) {
                uint32_t tbh[4], tbl[4];
                ldsm_x4(tbh, tKh + bKo[p] + kb);
                ldsm_x4(tbl, tKl + bKo[p] + kb);
                mma_bf16(s[2*p],   qh[kk], tbh[0], tbh[1]);
                mma_bf16(s[2*p],   qh[kk], tbl[0], tbl[1]);
                mma_bf16(s[2*p],   ql[kk], tbh[0], tbh[1]);
                mma_bf16(s[2*p+1], qh[kk], tbh[2], tbh[3]);
                mma_bf16(s[2*p+1], qh[kk], tbl[2], tbl[3]);
                mma_bf16(s[2*p+1], ql[kk], tbh[2], tbh[3]);
            }
        }
        if (t >= 2*qt) {
            const int k0 = t * 64;
            #pragma unroll
            for (int nf = 0; nf < 8; nf++) {
                const int cn = k0 + 8*nf + cnl;
                if (cn     > r0g)     s[nf][0] = -1e30f;
                if (cn + 1 > r0g)     s[nf][1] = -1e30f;
                if (cn     > r0g + 8) s[nf][2] = -1e30f;
                if (cn + 1 > r0g + 8) s[nf][3] = -1e30f;
            }
        }
    };

    // ---- softmax(t) + PV(t) from buffer b ----
    auto softmax_pv = [&](int b, float (&s)[8][4]) {
        float m0 = -1e30f, m1 = -1e30f;
        #pragma unroll
        for (int nf = 0; nf < 8; nf++) {
            m0 = fmaxf(m0, fmaxf(s[nf][0], s[nf][1]));
            m1 = fmaxf(m1, fmaxf(s[nf][2], s[nf][3]));
        }
        m0 = fmaxf(m0, __shfl_xor_sync(0xffffffffu, m0, 1));
        m0 = fmaxf(m0, __shfl_xor_sync(0xffffffffu, m0, 2));
        m1 = fmaxf(m1, __shfl_xor_sync(0xffffffffu, m1, 1));
        m1 = fmaxf(m1, __shfl_xor_sync(0xffffffffu, m1, 2));

        const float mn0 = fmaxf(m_run[0], m0);
        const float mn1 = fmaxf(m_run[1], m1);
        const float al0 = exp_fast(m_run[0] - mn0);
        const float al1 = exp_fast(m_run[1] - mn1);
        m_run[0] = mn0; m_run[1] = mn1;

        float sum0 = 0.f, sum1 = 0.f;
        uint32_t paH[4][4], paL[4][4];
        #pragma unroll
        for (int nf = 0; nf < 8; nf++) {
            float p0 = exp_fast(s[nf][0] - mn0);
            float p1 = exp_fast(s[nf][1] - mn0);
            float p2 = exp_fast(s[nf][2] - mn1);
            float p3 = exp_fast(s[nf][3] - mn1);
            sum0 += p0 + p1;
            sum1 += p2 + p3;
            const int kk = nf >> 1;
            const int u  = (nf & 1) << 1;
            split2(p0, p1, paH[kk][u],   paL[kk][u]);
            split2(p2, p3, paH[kk][u+1], paL[kk][u+1]);
        }
        sum0 += __shfl_xor_sync(0xffffffffu, sum0, 1);
        sum0 += __shfl_xor_sync(0xffffffffu, sum0, 2);
        sum1 += __shfl_xor_sync(0xffffffffu, sum1, 1);
        sum1 += __shfl_xor_sync(0xffffffffu, sum1, 2);
        l_run[0] = l_run[0] * al0 + sum0;
        l_run[1] = l_run[1] * al1 + sum1;

        #pragma unroll
        for (int nf = 0; nf < 8; nf++) {
            o[nf][0] *= al0; o[nf][1] *= al0;
            o[nf][2] *= al1; o[nf][3] *= al1;
        }

        const uint32_t tVh = kvb + (uint32_t)((b*4 + 2) * KTILE * 2);
        const uint32_t tVl = kvb + (uint32_t)((b*4 + 3) * KTILE * 2);
        #pragma unroll
        for (int kk = 0; kk < 4; kk++) {
            const uint32_t kr = (uint32_t)(kk * 16 * AST * 2);
            #pragma unroll
            for (int p = 0; p < 4; p++) {
                uint32_t tvh[4], tvl[4];
                ldsm_x4_t(tvh, tVh + bVo[p] + kr);
                ldsm_x4_t(tvl, tVl + bVo[p] + kr);
                mma_bf16(o[2*p],   paH[kk], tvh[0], tvh[1]);
                mma_bf16(o[2*p],   paH[kk], tvl[0], tvl[1]);
                mma_bf16(o[2*p],   paL[kk], tvh[0], tvh[1]);
                mma_bf16(o[2*p+1], paH[kk], tvh[2], tvh[3]);
                mma_bf16(o[2*p+1], paH[kk], tvl[2], tvl[3]);
                mma_bf16(o[2*p+1], paL[kk], tvh[2], tvh[3]);
            }
        }
    };

    // one pipelined step: consume cur(t), produce nxt(t+1), prefetch t+2
    auto step = [&](int t, float (&cur)[8][4], float (&nxt)[8][4]) {
        if (t + 1 < ntiles) {
            CP_WAIT0();            // KV(t+1) resident (this thread's part)
            __syncthreads();       // all threads' parts + PV(t-1) reads done
            smma(t + 1, (t + 1) % 3, nxt);
            if (t + 2 < ntiles) prefetch_kv(t + 2, (t + 2) % 3);
        }
        softmax_pv(t % 3, cur);    // FFMAs overlap in-flight S-MMA HMMAs
    };

    float sA[8][4], sB[8][4];
    smma(0, 0, sA);
    for (int jt = 0; jt < ntiles; jt += 2) {
        step(jt,     sA, sB);
        step(jt + 1, sB, sA);      // ntiles even -> always valid
    }

    // ---- epilogue: normalize, split, store ----
    const float inv0 = 1.f / l_run[0];
    const float inv1 = 1.f / l_run[1];
    #pragma unroll
    for (int nf = 0; nf < 8; nf++) {
        const int col = 8*nf + cnl;
        const size_t off0 = base + (size_t)r0g * D_DIM + col;
        const size_t off1 = off0 + (size_t)8 * D_DIM;
        uint32_t h, l;
        split2(o[nf][0] * inv0, o[nf][1] * inv0, h, l);
        *(uint32_t*)(g_oh + off0) = h;
        *(uint32_t*)(g_ol + off0) = l;
        split2(o[nf][2] * inv1, o[nf][3] * inv1, h, l);
        *(uint32_t*)(g_oh + off1) = h;
        *(uint32_t*)(g_ol + off1) = l;
    }
}

// ---------------------------------------------------------------------------
extern "C" void kernel_launch(void* const* d_in, const int* in_sizes, int n_in,
                              void* d_out, int out_size)
{
    (void)in_sizes; (void)n_in; (void)out_size;
    const float* x  = (const float*)d_in[0];
    const float* Wq = (const float*)d_in[2];
    const float* bq = (const float*)d_in[3];
    const float* Wk = (const float*)d_in[4];
    const float* bk = (const float*)d_in[5];
    const float* Wv = (const float*)d_in[6];
    const float* bv = (const float*)d_in[7];
    const float* Wo = (const float*)d_in[8];
    const float* bo = (const float*)d_in[9];
    float* out = (float*)d_out;

    __nv_bfloat16 *xh, *xl, *wh, *wl, *qh, *ql, *kh, *kl, *vh, *vl, *oh, *ol;
    cudaGetSymbolAddress((void**)&xh, g_xh);
    cudaGetSymbolAddress((void**)&xl, g_xl);
    cudaGetSymbolAddress((void**)&wh, g_wh);
    cudaGetSymbolAddress((void**)&wl, g_wl);
    cudaGetSymbolAddress((void**)&qh, g_qh);
    cudaGetSymbolAddress((void**)&ql, g_ql);
    cudaGetSymbolAddress((void**)&kh, g_kh);
    cudaGetSymbolAddress((void**)&kl, g_kl);
    cudaGetSymbolAddress((void**)&vh, g_vh);
    cudaGetSymbolAddress((void**)&vl, g_vl);
    cudaGetSymbolAddress((void**)&oh, g_oh);
    cudaGetSymbolAddress((void**)&ol, g_ol);

    cudaFuncSetAttribute(attn_mma,
                         cudaFuncAttributeMaxDynamicSharedMemorySize, ATTN_SMEM);
    cudaFuncSetAttribute(gemm_bf16x3<0>,
                         cudaFuncAttributeMaxDynamicSharedMemorySize, GEMM_SMEM);
    cudaFuncSetAttribute(gemm_bf16x3<1>,
                         cudaFuncAttributeMaxDynamicSharedMemorySize, GEMM_SMEM);

    const int WSZ = D_DIM * D_DIM;
    const int XN4 = (NROWS * D_DIM) / 4;
    const int WN4 = WSZ / 4;

    dim3 blk(256);

    split_kernel<<<(XN4 + 255) / 256, blk>>>(x,  xh, xl, XN4);
    split_kernel<<<(WN4 + 255) / 256, blk>>>(Wq, wh + 0*WSZ, wl + 0*WSZ, WN4);
    split_kernel<<<(WN4 + 255) / 256, blk>>>(Wk, wh + 1*WSZ, wl + 1*WSZ, WN4);
    split_kernel<<<(WN4 + 255) / 256, blk>>>(Wv, wh + 2*WSZ, wl + 2*WSZ, WN4);
    split_kernel<<<(WN4 + 255) / 256, blk>>>(Wo, wh + 3*WSZ, wl + 3*WSZ, WN4);

    dim3 gG(D_DIM / 128, NROWS / 128);      // (8, 64)
    gemm_bf16x3<1><<<gG, blk, GEMM_SMEM>>>(xh, xl, wh + 0*WSZ, wl + 0*WSZ, bq,
                                           0.125f, nullptr, qh, ql, D_DIM);
    gemm_bf16x3<1><<<gG, blk, GEMM_SMEM>>>(xh, xl, wh + 1*WSZ, wl + 1*WSZ, bk,
                                           1.0f, nullptr, kh, kl, D_DIM);
    gemm_bf16x3<1><<<gG, blk, GEMM_SMEM>>>(xh, xl, wh + 2*WSZ, wl + 2*WSZ, bv,
                                           1.0f, nullptr, vh, vl, D_DIM);

    dim3 gA(S_LEN / 128, B_SZ * NH);        // (16, 64)
    attn_mma<<<gA, blk, ATTN_SMEM>>>();

    gemm_bf16x3<0><<<gG, blk, GEMM_SMEM>>>(oh, ol, wh + 3*WSZ, wl + 3*WSZ, bo,
                                           1.0f, out, nullptr, nullptr, D_DIM);
}